// round 11
// baseline (speedup 1.0000x reference)
#include <cuda_runtime.h>
#include <cuda_fp16.h>
#include <math.h>
#include <stdint.h>

// Problem constants
#define Bsz 2
#define Tq  2048
#define Cdim 1024
#define Hh  16
#define Dd  64
#define Mrows (Bsz*Tq)   // 4096

// ---------------------------------------------------------------------------
// Device-global scratch (sanctioned no-alloc path)
// ---------------------------------------------------------------------------
__device__ __align__(16) __half g_xh[Mrows*Cdim];
__device__ __align__(16) __half g_Wh[4*Cdim*Cdim];   // Wq,Wk,Wv,Wp packed
__device__ __align__(16) __half g_Qh[Mrows*Cdim];
__device__ __align__(16) __half g_Kh[Mrows*Cdim];
__device__ __align__(16) __half g_Vh[Mrows*Cdim];
__device__ __align__(16) __half g_Oh[Mrows*Cdim];

// ---------------------------------------------------------------------------
// Helpers (family-portable ISA)
// ---------------------------------------------------------------------------
__device__ __forceinline__ uint32_t smem_u32(const void* p) {
    uint32_t a;
    asm("{ .reg .u64 t; cvta.to.shared.u64 t, %1; cvt.u32.u64 %0, t; }"
        : "=r"(a) : "l"(p));
    return a;
}
__device__ __forceinline__ void cp16(uint32_t dst, const void* src) {
    asm volatile("cp.async.cg.shared.global [%0], [%1], 16;"
                 :: "r"(dst), "l"(src));
}
__device__ __forceinline__ void cp_commit() {
    asm volatile("cp.async.commit_group;");
}
template<int N> __device__ __forceinline__ void cp_wait() {
    asm volatile("cp.async.wait_group %0;" :: "n"(N));
}
__device__ __forceinline__ void mma_h(
    float& c0, float& c1, float& c2, float& c3,
    uint32_t a0, uint32_t a1, uint32_t a2, uint32_t a3,
    uint32_t b0, uint32_t b1)
{
    asm volatile(
        "mma.sync.aligned.m16n8k16.row.col.f32.f16.f16.f32 "
        "{%0,%1,%2,%3}, {%4,%5,%6,%7}, {%8,%9}, {%0,%1,%2,%3};"
        : "+f"(c0), "+f"(c1), "+f"(c2), "+f"(c3)
        : "r"(a0), "r"(a1), "r"(a2), "r"(a3), "r"(b0), "r"(b1));
}
__device__ __forceinline__ void ldsm4(
    uint32_t& r0, uint32_t& r1, uint32_t& r2, uint32_t& r3, uint32_t addr)
{
    asm volatile("ldmatrix.sync.aligned.m8n8.x4.shared.b16 {%0,%1,%2,%3}, [%4];"
        : "=r"(r0), "=r"(r1), "=r"(r2), "=r"(r3) : "r"(addr));
}
__device__ __forceinline__ void ldsm4t(
    uint32_t& r0, uint32_t& r1, uint32_t& r2, uint32_t& r3, uint32_t addr)
{
    asm volatile("ldmatrix.sync.aligned.m8n8.x4.trans.shared.b16 {%0,%1,%2,%3}, [%4];"
        : "=r"(r0), "=r"(r1), "=r"(r2), "=r"(r3) : "r"(addr));
}
__device__ __forceinline__ void ldsm2t(uint32_t& r0, uint32_t& r1, uint32_t addr)
{
    asm volatile("ldmatrix.sync.aligned.m8n8.x2.trans.shared.b16 {%0,%1}, [%2];"
        : "=r"(r0), "=r"(r1) : "r"(addr));
}
__device__ __forceinline__ uint32_t pack2h(float lo, float hi) {
    uint32_t r;
    asm("cvt.rn.f16x2.f32 %0, %1, %2;" : "=r"(r) : "f"(hi), "f"(lo));
    return r;
}
__device__ __forceinline__ float ex2f(float x) {
    float r;
    asm("ex2.approx.ftz.f32 %0, %1;" : "=f"(r) : "f"(x));
    return r;
}

// ---------------------------------------------------------------------------
// fp32 -> fp16 converts
// ---------------------------------------------------------------------------
__global__ void cvt_kernel(const float* __restrict__ src,
                           __half* __restrict__ dst, int n)
{
    int i = (blockIdx.x * blockDim.x + threadIdx.x) * 8;
    if (i >= n) return;
    float4 a = *(const float4*)(src + i);
    float4 b = *(const float4*)(src + i + 4);
    uint4 o;
    o.x = pack2h(a.x, a.y); o.y = pack2h(a.z, a.w);
    o.z = pack2h(b.x, b.y); o.w = pack2h(b.z, b.w);
    *(uint4*)(dst + i) = o;
}

__global__ void cvt4_kernel(const float* __restrict__ s0,
                            const float* __restrict__ s1,
                            const float* __restrict__ s2,
                            const float* __restrict__ s3,
                            __half* __restrict__ dst, int n)
{
    const float* s = (blockIdx.y == 0) ? s0 : (blockIdx.y == 1) ? s1
                   : (blockIdx.y == 2) ? s2 : s3;
    int i = (blockIdx.x * blockDim.x + threadIdx.x) * 8;
    if (i >= n) return;
    const size_t off = (size_t)blockIdx.y * n;
    float4 a = *(const float4*)(s + i);
    float4 b = *(const float4*)(s + i + 4);
    uint4 o;
    o.x = pack2h(a.x, a.y); o.y = pack2h(a.z, a.w);
    o.z = pack2h(b.x, b.y); o.w = pack2h(b.z, b.w);
    *(uint4*)(dst + off + i) = o;
}

// ---------------------------------------------------------------------------
// GEMM v2, fp16 mma.sync. CTA 64x128, 128 threads (4 warps), each warp the
// proven 64x32 microkernel (n-band = wid*32). BK=64, 2-stage cp.async ring.
// launch_bounds(128,3): 12 warps/SM and ~170-reg budget so ptxas can
// software-pipeline ldsm->mma (the round-5..10 GEMM ran at a full RF and
// couldn't). mode 0: fused QKV (W [3072,1024]); Q pre-scaled 0.125*log2e.
// mode 1: output projection, fp32 Cout, bias b0.
// ---------------------------------------------------------------------------
#define GPg 72
#define A_ARR (64*GPg*2)            // 9216 bytes
#define B_ARR (128*GPg*2)           // 18432 bytes
#define STGB  (A_ARR + B_ARR)       // 27648 per stage
#define GEMM_SMEM2 (2*STGB)         // 55296

__global__ __launch_bounds__(128, 3) void gemm_h(
    const __half* __restrict__ A, const __half* __restrict__ W,
    const float* __restrict__ b0, const float* __restrict__ b1,
    const float* __restrict__ b2, float* __restrict__ Cout, int mode)
{
    extern __shared__ char sm[];
    const uint32_t sb = smem_u32(sm);
    const int tid = threadIdx.x, lane = tid & 31, wid = tid >> 5;  // 4 warps
    const int m0 = blockIdx.y * 64, n0 = blockIdx.x * 128;

    // staging coords: A 64 rows (2 thr/row, 32 halfs each = 4 cp16),
    //                 B 128 rows (1 thr/row, 64 halfs = 8 cp16)
    const int arow = tid >> 1, acolh = (tid & 1) * 32;
    const uint32_t aoff = (uint32_t)(arow * GPg + acolh) * 2;
    const uint32_t boff = (uint32_t)A_ARR + (uint32_t)(tid * GPg) * 2;
    const __half* Ar = A + (size_t)(m0 + arow) * Cdim + acolh;
    const __half* Wr = W + (size_t)(n0 + tid) * Cdim;

#define STG(kc, slot) do {                                        \
        uint32_t st_ = sb + (slot) * STGB;                        \
        cp16(st_ + aoff,      Ar + (kc));                         \
        cp16(st_ + aoff + 16, Ar + (kc) + 8);                     \
        cp16(st_ + aoff + 32, Ar + (kc) + 16);                    \
        cp16(st_ + aoff + 48, Ar + (kc) + 24);                    \
        cp16(st_ + boff,       Wr + (kc));                        \
        cp16(st_ + boff + 16,  Wr + (kc) + 8);                    \
        cp16(st_ + boff + 32,  Wr + (kc) + 16);                   \
        cp16(st_ + boff + 48,  Wr + (kc) + 24);                   \
        cp16(st_ + boff + 64,  Wr + (kc) + 32);                   \
        cp16(st_ + boff + 80,  Wr + (kc) + 40);                   \
        cp16(st_ + boff + 96,  Wr + (kc) + 48);                   \
        cp16(st_ + boff + 112, Wr + (kc) + 56);                   \
        cp_commit();                                              \
    } while (0)

    float acc[4][4][4];
#pragma unroll
    for (int a = 0; a < 4; a++)
#pragma unroll
        for (int b = 0; b < 4; b++)
#pragma unroll
            for (int c = 0; c < 4; c++) acc[a][b][c] = 0.f;

    STG(0, 0);

    for (int kt = 0; kt < 16; kt++) {
        const int cur = kt & 1;
        if (kt < 15) {                 // stage next chunk into the other buffer
            STG((kt + 1) * 64, cur ^ 1);   // safe: that buffer's readers
            cp_wait<1>();                  // synced at end of chunk kt-1
        } else {
            cp_wait<0>();
        }
        __syncthreads();               // chunk kt resident

        const uint32_t stb = sb + cur * STGB;
#pragma unroll
        for (int s = 0; s < 4; s++) {
            const uint32_t cg = s * 16 + ((lane >> 4) << 3);
            uint32_t bf[2][4], af[4][4];
#pragma unroll
            for (int ntp = 0; ntp < 2; ntp++)
                ldsm4(bf[ntp][0], bf[ntp][1], bf[ntp][2], bf[ntp][3],
                      stb + A_ARR +
                      ((wid * 32 + ntp * 16 + (lane & 15)) * GPg + cg) * 2);
#pragma unroll
            for (int mt = 0; mt < 4; mt++)
                ldsm4(af[mt][0], af[mt][1], af[mt][2], af[mt][3],
                      stb + ((mt * 16 + (lane & 15)) * GPg + cg) * 2);
#pragma unroll
            for (int mt = 0; mt < 4; mt++)
#pragma unroll
                for (int nt = 0; nt < 4; nt++) {
                    float* c = acc[mt][nt];
                    mma_h(c[0], c[1], c[2], c[3],
                          af[mt][0], af[mt][1], af[mt][2], af[mt][3],
                          bf[nt >> 1][nt & 1], bf[nt >> 1][(nt & 1) + 2]);
                }
        }
        __syncthreads();               // all reads of buffer cur done
    }
#undef STG

    // epilogue
    const int mat = n0 >> 10;  // constant per CTA (mode 0)
    const float* bb = (mat == 0) ? b0 : (mat == 1) ? b1 : b2;
    __half* dsth = (mat == 0) ? g_Qh : (mat == 1) ? g_Kh : g_Vh;
    // Q scale folds 1/sqrt(D) AND log2(e) so attention uses ex2 directly
    const float scale = (mat == 0) ? 0.125f * 1.4426950408889634f : 1.0f;

#pragma unroll
    for (int mt = 0; mt < 4; mt++) {
#pragma unroll
        for (int nt = 0; nt < 4; nt++) {
            float* c = acc[mt][nt];
            const int row = m0 + mt * 16 + (lane >> 2);
            const int col = n0 + wid * 32 + nt * 8 + 2 * (lane & 3);
            if (mode == 1) {
                const float bv0 = b0[col], bv1 = b0[col + 1];
                *(float2*)(Cout + (size_t)row * Cdim + col) =
                    make_float2(c[0] + bv0, c[1] + bv1);
                *(float2*)(Cout + (size_t)(row + 8) * Cdim + col) =
                    make_float2(c[2] + bv0, c[3] + bv1);
            } else {
                const int mc = col & 1023;
                const float bv0 = bb[mc], bv1 = bb[mc + 1];
                const float v00 = (c[0] + bv0) * scale, v01 = (c[1] + bv1) * scale;
                const float v10 = (c[2] + bv0) * scale, v11 = (c[3] + bv1) * scale;
                const int hh = mc >> 6, d = mc & 63;
                const int bb0 = row >> 11, t0 = row & 2047;
                const int bb1 = (row + 8) >> 11, t1 = (row + 8) & 2047;
                const size_t i0 = (((size_t)(bb0 * Hh + hh)) * Tq + t0) * Dd + d;
                const size_t i1 = (((size_t)(bb1 * Hh + hh)) * Tq + t1) * Dd + d;
                *(uint32_t*)(dsth + i0) = pack2h(v00, v01);
                *(uint32_t*)(dsth + i1) = pack2h(v10, v11);
            }
        }
    }
}

// ---------------------------------------------------------------------------
// Flash attention, fp16 mma.sync, static softmax — UNCHANGED from round 10
// (best known: 118 us). Round-8 structure + bare ex2 (Q carries 0.125*log2e).
// ---------------------------------------------------------------------------
#define QP 72
#define QTILE (128*QP*2)           // 18432
#define KVARR (64*QP*2)            // 9216
#define OFF_Q 0
#define OFF_KB(s) (QTILE + (s)*2*KVARR)
#define OFF_VB(s) (QTILE + (s)*2*KVARR + KVARR)
#define OFF_MK (QTILE + 6*KVARR)
#define ATT_SMEM_B (OFF_MK + 3*64*4)   // 74496

__global__ __launch_bounds__(256, 2) void attn_h(const int* __restrict__ mask)
{
    extern __shared__ char sm[];
    const uint32_t sb = smem_u32(sm);
    const int tid = threadIdx.x, lane = tid & 31, wid = tid >> 5;
    const int bh = blockIdx.y;
    const int b  = bh >> 4, h = bh & 15;
    const int q0 = blockIdx.x * 128;
    int* Mk = (int*)(sm + OFF_MK);

    // ones columns (V cols 64..71, all 3 buffers) — written once.
    if (tid < 192) {
        const int s = tid >> 6, row = tid & 63;
        uint32_t* p = (uint32_t*)(sm + OFF_VB(s) + (row * QP + 64) * 2);
        p[0] = 0x3C003C00u; p[1] = 0x3C003C00u;
        p[2] = 0x3C003C00u; p[3] = 0x3C003C00u;
    }

    // Q staging: 128 rows, 2 threads/row, 4 cp16 each
    {
        const int qrow = tid >> 1, qcol = (tid & 1) * 32;
        const uint32_t qoff = (uint32_t)(qrow * QP + qcol) * 2;
        const __half* Qg = g_Qh + ((size_t)bh * Tq + q0 + qrow) * Dd + qcol;
#pragma unroll
        for (int j = 0; j < 4; j++)
            cp16(sb + OFF_Q + qoff + j * 16, Qg + j * 8);
        cp_commit();
    }

    // K/V staging coords: 64 rows, 4 threads/row, 2 cp16 per array
    const int krow = tid >> 2, kcol = (tid & 3) * 16;
    const uint32_t koff = (uint32_t)(krow * QP + kcol) * 2;

#define STAGEKV(kt, slot) do {                                                 \
        const __half* Kg_ = g_Kh + ((size_t)bh * Tq + (kt) * 64 + krow) * Dd + kcol; \
        const __half* Vg_ = g_Vh + ((size_t)bh * Tq + (kt) * 64 + krow) * Dd + kcol; \
        cp16(sb + OFF_KB(slot) + koff,      Kg_);                              \
        cp16(sb + OFF_KB(slot) + koff + 16, Kg_ + 8);                          \
        cp16(sb + OFF_VB(slot) + koff,      Vg_);                              \
        cp16(sb + OFF_VB(slot) + koff + 16, Vg_ + 8);                          \
        if (tid < 64) Mk[(slot) * 64 + tid] = mask[b * Tq + (kt) * 64 + tid];  \
        cp_commit();                                                           \
    } while (0)

    STAGEKV(0, 0);
    STAGEKV(1, 1);
    cp_wait<2>();       // Q landed (pending: s0, s1)
    __syncthreads();

    // hoist Q fragments (loop-invariant): warp covers rows wid*16..wid*16+15
    uint32_t qf[4][4];
#pragma unroll
    for (int ks = 0; ks < 4; ks++)
        ldsm4(qf[ks][0], qf[ks][1], qf[ks][2], qf[ks][3],
              sb + OFF_Q +
              ((wid * 16 + (lane & 15)) * QP + ks * 16 + ((lane >> 4) << 3)) * 2);

    float o[8][4];
#pragma unroll
    for (int nt = 0; nt < 8; nt++)
#pragma unroll
        for (int c = 0; c < 4; c++) o[nt][c] = 0.f;
    float ssum[4] = {0.f, 0.f, 0.f, 0.f};   // row-sum fragment (ones-col MMA)

    const int NT = Tq / 64;   // 32
    int r = 0, snext = 2;
    for (int kt = 0; kt < NT; kt++) {
        if (kt < NT - 1) cp_wait<1>(); else cp_wait<0>();
        __syncthreads();   // buffer r ready; also releases slot snext
        if (kt + 2 < NT) {
            STAGEKV(kt + 2, snext);
            snext = (snext == 2) ? 0 : snext + 1;
        }

        // ---- S = Q K^T ----
        float s[8][4];
#pragma unroll
        for (int nt = 0; nt < 8; nt++)
#pragma unroll
            for (int c = 0; c < 4; c++) s[nt][c] = 0.f;

#pragma unroll
        for (int ks = 0; ks < 4; ks++) {
#pragma unroll
            for (int ntp = 0; ntp < 4; ntp++) {
                uint32_t k0, k1, k2, k3;
                ldsm4(k0, k1, k2, k3,
                      sb + OFF_KB(r) +
                      ((ntp * 16 + (lane & 15)) * QP + ks * 16 + ((lane >> 4) << 3)) * 2);
                float* sa = s[2 * ntp];
                float* sc = s[2 * ntp + 1];
                mma_h(sa[0], sa[1], sa[2], sa[3],
                      qf[ks][0], qf[ks][1], qf[ks][2], qf[ks][3], k0, k2);
                mma_h(sc[0], sc[1], sc[2], sc[3],
                      qf[ks][0], qf[ks][1], qf[ks][2], qf[ks][3], k1, k3);
            }
        }

        // ---- mask (warp-uniform all-ones fast path) ----
        const int* mk = Mk + r * 64;
        const bool allone = __all_sync(0xffffffffu,
                (mk[lane] != 0) & (mk[lane + 32] != 0));
        if (!allone) {
            const int c0 = 2 * (lane & 3);
#pragma unroll
            for (int nt = 0; nt < 8; nt++) {
                if (!mk[nt * 8 + c0])     { s[nt][0] = -1e30f; s[nt][2] = -1e30f; }
                if (!mk[nt * 8 + c0 + 1]) { s[nt][1] = -1e30f; s[nt][3] = -1e30f; }
            }
        }

        // ---- static softmax: P = 2^S (Q carries log2e; bare MUFU) ----
#pragma unroll
        for (int nt = 0; nt < 8; nt++) {
            s[nt][0] = ex2f(s[nt][0]);
            s[nt][1] = ex2f(s[nt][1]);
            s[nt][2] = ex2f(s[nt][2]);
            s[nt][3] = ex2f(s[nt][3]);
        }

        // ---- O += P V ; ssum += P @ ones ----
#pragma unroll
        for (int ks = 0; ks < 4; ks++) {
            uint32_t pa0 = pack2h(s[2 * ks][0],     s[2 * ks][1]);
            uint32_t pa1 = pack2h(s[2 * ks][2],     s[2 * ks][3]);
            uint32_t pa2 = pack2h(s[2 * ks + 1][0], s[2 * ks + 1][1]);
            uint32_t pa3 = pack2h(s[2 * ks + 1][2], s[2 * ks + 1][3]);

            uint32_t u0, u1;   // ones-column B fragment (cols 64..71)
            ldsm2t(u0, u1,
                   sb + OFF_VB(r) + ((ks * 16 + (lane & 15)) * QP + 64) * 2);
            mma_h(ssum[0], ssum[1], ssum[2], ssum[3], pa0, pa1, pa2, pa3, u0, u1);

#pragma unroll
            for (int ntp = 0; ntp < 4; ntp++) {
                uint32_t v0, v1, v2, v3;
                ldsm4t(v0, v1, v2, v3,
                       sb + OFF_VB(r) +
                       ((ks * 16 + (lane & 15)) * QP + ntp * 16 + ((lane >> 4) << 3)) * 2);
                float* oa = o[2 * ntp];
                float* ob = o[2 * ntp + 1];
                mma_h(oa[0], oa[1], oa[2], oa[3], pa0, pa1, pa2, pa3, v0, v1);
                mma_h(ob[0], ob[1], ob[2], ob[3], pa0, pa1, pa2, pa3, v2, v3);
            }
        }
        r = (r == 2) ? 0 : r + 1;
    }
#undef STAGEKV

    // ---- finalize: ssum fragment already holds exact row sums ----
    const float inv0 = 1.0f / ssum[0], inv1 = 1.0f / ssum[2];
    const int gr0 = q0 + wid * 16 + (lane >> 2);
#pragma unroll
    for (int nt = 0; nt < 8; nt++) {
        const int col = h * Dd + nt * 8 + 2 * (lane & 3);
        const size_t i0 = ((size_t)b * Tq + gr0) * Cdim + col;
        const size_t i1 = ((size_t)b * Tq + gr0 + 8) * Cdim + col;
        *(uint32_t*)(g_Oh + i0) = pack2h(o[nt][0] * inv0, o[nt][1] * inv0);
        *(uint32_t*)(g_Oh + i1) = pack2h(o[nt][2] * inv1, o[nt][3] * inv1);
    }
}

// ---------------------------------------------------------------------------
extern "C" void kernel_launch(void* const* d_in, const int* in_sizes, int n_in,
                              void* d_out, int out_size)
{
    (void)in_sizes; (void)n_in; (void)out_size;
    const float* x    = (const float*)d_in[0];
    const int*   mask = (const int*)d_in[1];
    const float* Wq = (const float*)d_in[2];
    const float* bq = (const float*)d_in[3];
    const float* Wk = (const float*)d_in[4];
    const float* bk = (const float*)d_in[5];
    const float* Wv = (const float*)d_in[6];
    const float* bv = (const float*)d_in[7];
    const float* Wp = (const float*)d_in[8];
    const float* bp = (const float*)d_in[9];
    float* out = (float*)d_out;

    static bool init = false;
    static __half *xh, *wh, *oh;
    if (!init) {
        cudaFuncSetAttribute(gemm_h,
            cudaFuncAttributeMaxDynamicSharedMemorySize, GEMM_SMEM2);
        cudaFuncSetAttribute(attn_h,
            cudaFuncAttributeMaxDynamicSharedMemorySize, ATT_SMEM_B);
        cudaGetSymbolAddress((void**)&xh, g_xh);
        cudaGetSymbolAddress((void**)&wh, g_Wh);
        cudaGetSymbolAddress((void**)&oh, g_Oh);
        init = true;
    }

    const int NX = Mrows * Cdim;   // 4194304
    const int NW = Cdim * Cdim;    // 1048576
    const size_t WN = (size_t)NW;

    cvt_kernel<<<NX / 2048, 256>>>(x, xh, NX);
    {
        dim3 g(NW / 2048, 4);
        cvt4_kernel<<<g, 256>>>(Wq, Wk, Wv, Wp, wh, NW);
    }

    // fused QKV projection: N = 3072 over packed Wq|Wk|Wv
    {
        dim3 g(3 * Cdim / 128, Mrows / 64);   // (24, 64)
        gemm_h<<<g, 128, GEMM_SMEM2>>>(xh, wh, bq, bk, bv, nullptr, 0);
    }

    {
        dim3 g(Tq / 128, Bsz * Hh);           // (16, 32)
        attn_h<<<g, 256, ATT_SMEM_B>>>(mask);
    }

    // output projection
    {
        dim3 g(Cdim / 128, Mrows / 64);       // (8, 64)
        gemm_h<<<g, 128, GEMM_SMEM2>>>(oh, wh + 3 * WN, bp, bp, bp, out, 1);
    }
}

// round 12
// speedup vs baseline: 1.0594x; 1.0594x over previous
#include <cuda_runtime.h>
#include <cuda_fp16.h>
#include <math.h>
#include <stdint.h>

// Problem constants
#define Bsz 2
#define Tq  2048
#define Cdim 1024
#define Hh  16
#define Dd  64
#define Mrows (Bsz*Tq)   // 4096

// ---------------------------------------------------------------------------
// Device-global scratch (sanctioned no-alloc path)
// ---------------------------------------------------------------------------
__device__ __align__(16) __half g_xh[Mrows*Cdim];
__device__ __align__(16) __half g_Wh[4*Cdim*Cdim];   // Wq,Wk,Wv,Wp packed
__device__ __align__(16) __half g_Qh[Mrows*Cdim];
__device__ __align__(16) __half g_Kh[Mrows*Cdim];
__device__ __align__(16) __half g_Vh[Mrows*Cdim];
__device__ __align__(16) __half g_Oh[Mrows*Cdim];

// ---------------------------------------------------------------------------
// Helpers (family-portable ISA)
// ---------------------------------------------------------------------------
__device__ __forceinline__ uint32_t smem_u32(const void* p) {
    uint32_t a;
    asm("{ .reg .u64 t; cvta.to.shared.u64 t, %1; cvt.u32.u64 %0, t; }"
        : "=r"(a) : "l"(p));
    return a;
}
__device__ __forceinline__ void cp16(uint32_t dst, const void* src) {
    asm volatile("cp.async.cg.shared.global [%0], [%1], 16;"
                 :: "r"(dst), "l"(src));
}
__device__ __forceinline__ void cp_commit() {
    asm volatile("cp.async.commit_group;");
}
template<int N> __device__ __forceinline__ void cp_wait() {
    asm volatile("cp.async.wait_group %0;" :: "n"(N));
}
__device__ __forceinline__ void mma_h(
    float& c0, float& c1, float& c2, float& c3,
    uint32_t a0, uint32_t a1, uint32_t a2, uint32_t a3,
    uint32_t b0, uint32_t b1)
{
    asm volatile(
        "mma.sync.aligned.m16n8k16.row.col.f32.f16.f16.f32 "
        "{%0,%1,%2,%3}, {%4,%5,%6,%7}, {%8,%9}, {%0,%1,%2,%3};"
        : "+f"(c0), "+f"(c1), "+f"(c2), "+f"(c3)
        : "r"(a0), "r"(a1), "r"(a2), "r"(a3), "r"(b0), "r"(b1));
}
__device__ __forceinline__ void ldsm4(
    uint32_t& r0, uint32_t& r1, uint32_t& r2, uint32_t& r3, uint32_t addr)
{
    asm volatile("ldmatrix.sync.aligned.m8n8.x4.shared.b16 {%0,%1,%2,%3}, [%4];"
        : "=r"(r0), "=r"(r1), "=r"(r2), "=r"(r3) : "r"(addr));
}
__device__ __forceinline__ void ldsm4t(
    uint32_t& r0, uint32_t& r1, uint32_t& r2, uint32_t& r3, uint32_t addr)
{
    asm volatile("ldmatrix.sync.aligned.m8n8.x4.trans.shared.b16 {%0,%1,%2,%3}, [%4];"
        : "=r"(r0), "=r"(r1), "=r"(r2), "=r"(r3) : "r"(addr));
}
__device__ __forceinline__ void ldsm2t(uint32_t& r0, uint32_t& r1, uint32_t addr)
{
    asm volatile("ldmatrix.sync.aligned.m8n8.x2.trans.shared.b16 {%0,%1}, [%2];"
        : "=r"(r0), "=r"(r1) : "r"(addr));
}
__device__ __forceinline__ uint32_t pack2h(float lo, float hi) {
    uint32_t r;
    asm("cvt.rn.f16x2.f32 %0, %1, %2;" : "=r"(r) : "f"(hi), "f"(lo));
    return r;
}
__device__ __forceinline__ float ex2f(float x) {
    float r;
    asm("ex2.approx.ftz.f32 %0, %1;" : "=f"(r) : "f"(x));
    return r;
}

// ---------------------------------------------------------------------------
// fp32 -> fp16 converts
// ---------------------------------------------------------------------------
__global__ void cvt_kernel(const float* __restrict__ src,
                           __half* __restrict__ dst, int n)
{
    int i = (blockIdx.x * blockDim.x + threadIdx.x) * 8;
    if (i >= n) return;
    float4 a = *(const float4*)(src + i);
    float4 b = *(const float4*)(src + i + 4);
    uint4 o;
    o.x = pack2h(a.x, a.y); o.y = pack2h(a.z, a.w);
    o.z = pack2h(b.x, b.y); o.w = pack2h(b.z, b.w);
    *(uint4*)(dst + i) = o;
}

__global__ void cvt4_kernel(const float* __restrict__ s0,
                            const float* __restrict__ s1,
                            const float* __restrict__ s2,
                            const float* __restrict__ s3,
                            __half* __restrict__ dst, int n)
{
    const float* s = (blockIdx.y == 0) ? s0 : (blockIdx.y == 1) ? s1
                   : (blockIdx.y == 2) ? s2 : s3;
    int i = (blockIdx.x * blockDim.x + threadIdx.x) * 8;
    if (i >= n) return;
    const size_t off = (size_t)blockIdx.y * n;
    float4 a = *(const float4*)(s + i);
    float4 b = *(const float4*)(s + i + 4);
    uint4 o;
    o.x = pack2h(a.x, a.y); o.y = pack2h(a.z, a.w);
    o.z = pack2h(b.x, b.y); o.w = pack2h(b.z, b.w);
    *(uint4*)(dst + off + i) = o;
}

// ---------------------------------------------------------------------------
// GEMM v3, fp16 mma.sync. CTA 128x128 (same L2 footprint as the proven
// round-10 GEMM), but 128 threads / 4 warps in a 2(m)x2(n) grid of 64x64
// warp tiles: mma:ldsm ratio 128:32 (was 64:24) and a 255-reg budget
// (launch_bounds(128,2)) so ptxas can pipeline ldsm->mma. BK=64, 3-stage
// cp.async ring, single __syncthreads per chunk, prefetch issued right
// after the barrier. 2 CTAs/SM (smem 110.6KB each).
// mode 0: fused QKV (W [3072,1024]); Q pre-scaled 0.125*log2e.
// mode 1: output projection, fp32 Cout, bias b0.
// ---------------------------------------------------------------------------
#define GPg 72
#define A_ARR (128*GPg*2)           // 18432 bytes per operand array
#define STGB  (2*A_ARR)             // 36864 per stage (A + W)
#define GEMM_SMEM2 (3*STGB)         // 110592

__global__ __launch_bounds__(128, 2) void gemm_h(
    const __half* __restrict__ A, const __half* __restrict__ W,
    const float* __restrict__ b0, const float* __restrict__ b1,
    const float* __restrict__ b2, float* __restrict__ Cout, int mode)
{
    extern __shared__ char sm[];
    const uint32_t sb = smem_u32(sm);
    const int tid = threadIdx.x, lane = tid & 31, wid = tid >> 5;  // 4 warps
    const int wm = wid & 1, wn = wid >> 1;                         // 2x2
    const int m0 = blockIdx.y * 128, n0 = blockIdx.x * 128;

    // staging: 1 thread per row, 64 halfs = 8 cp16 each for A and W
    const uint32_t aoff = (uint32_t)(tid * GPg) * 2;
    const uint32_t boff = (uint32_t)A_ARR + aoff;
    const __half* Ar = A + (size_t)(m0 + tid) * Cdim;
    const __half* Wr = W + (size_t)(n0 + tid) * Cdim;

#define STG(kc, slot) do {                                        \
        uint32_t st_ = sb + (slot) * STGB;                        \
        cp16(st_ + aoff,       Ar + (kc));                        \
        cp16(st_ + aoff + 16,  Ar + (kc) + 8);                    \
        cp16(st_ + aoff + 32,  Ar + (kc) + 16);                   \
        cp16(st_ + aoff + 48,  Ar + (kc) + 24);                   \
        cp16(st_ + aoff + 64,  Ar + (kc) + 32);                   \
        cp16(st_ + aoff + 80,  Ar + (kc) + 40);                   \
        cp16(st_ + aoff + 96,  Ar + (kc) + 48);                   \
        cp16(st_ + aoff + 112, Ar + (kc) + 56);                   \
        cp16(st_ + boff,       Wr + (kc));                        \
        cp16(st_ + boff + 16,  Wr + (kc) + 8);                    \
        cp16(st_ + boff + 32,  Wr + (kc) + 16);                   \
        cp16(st_ + boff + 48,  Wr + (kc) + 24);                   \
        cp16(st_ + boff + 64,  Wr + (kc) + 32);                   \
        cp16(st_ + boff + 80,  Wr + (kc) + 40);                   \
        cp16(st_ + boff + 96,  Wr + (kc) + 48);                   \
        cp16(st_ + boff + 112, Wr + (kc) + 56);                   \
        cp_commit();                                              \
    } while (0)

    float acc[4][8][4];
#pragma unroll
    for (int a = 0; a < 4; a++)
#pragma unroll
        for (int b = 0; b < 8; b++)
#pragma unroll
            for (int c = 0; c < 4; c++) acc[a][b][c] = 0.f;

    STG(0, 0); STG(64, 1);

    int slot_next = 2;
    for (int kt = 0; kt < 16; kt++) {
        if (kt < 14) cp_wait<1>(); else cp_wait<0>();
        __syncthreads();               // chunk kt resident; slot_next free
        if (kt + 2 < 16) {
            STG((kt + 2) * 64, slot_next);
            slot_next = (slot_next == 2) ? 0 : slot_next + 1;
        }

        const int sl = kt - (kt / 3) * 3;   // kt mod 3
        const uint32_t stb = sb + sl * STGB;

#pragma unroll
        for (int s = 0; s < 4; s++) {
            const uint32_t cg = s * 16 + ((lane >> 4) << 3);
            uint32_t bf[4][4], af[4][4];
#pragma unroll
            for (int ntp = 0; ntp < 4; ntp++)
                ldsm4(bf[ntp][0], bf[ntp][1], bf[ntp][2], bf[ntp][3],
                      stb + A_ARR +
                      ((wn * 64 + ntp * 16 + (lane & 15)) * GPg + cg) * 2);
#pragma unroll
            for (int mt = 0; mt < 4; mt++)
                ldsm4(af[mt][0], af[mt][1], af[mt][2], af[mt][3],
                      stb + ((wm * 64 + mt * 16 + (lane & 15)) * GPg + cg) * 2);
#pragma unroll
            for (int mt = 0; mt < 4; mt++)
#pragma unroll
                for (int nt = 0; nt < 8; nt++) {
                    float* c = acc[mt][nt];
                    mma_h(c[0], c[1], c[2], c[3],
                          af[mt][0], af[mt][1], af[mt][2], af[mt][3],
                          bf[nt >> 1][nt & 1], bf[nt >> 1][(nt & 1) + 2]);
                }
        }
    }
#undef STG

    // epilogue
    const int mat = n0 >> 10;  // constant per CTA (mode 0)
    const float* bb = (mat == 0) ? b0 : (mat == 1) ? b1 : b2;
    __half* dsth = (mat == 0) ? g_Qh : (mat == 1) ? g_Kh : g_Vh;
    // Q scale folds 1/sqrt(D) AND log2(e) so attention uses ex2 directly
    const float scale = (mat == 0) ? 0.125f * 1.4426950408889634f : 1.0f;

#pragma unroll
    for (int mt = 0; mt < 4; mt++) {
#pragma unroll
        for (int nt = 0; nt < 8; nt++) {
            float* c = acc[mt][nt];
            const int row = m0 + wm * 64 + mt * 16 + (lane >> 2);
            const int col = n0 + wn * 64 + nt * 8 + 2 * (lane & 3);
            if (mode == 1) {
                const float bv0 = b0[col], bv1 = b0[col + 1];
                *(float2*)(Cout + (size_t)row * Cdim + col) =
                    make_float2(c[0] + bv0, c[1] + bv1);
                *(float2*)(Cout + (size_t)(row + 8) * Cdim + col) =
                    make_float2(c[2] + bv0, c[3] + bv1);
            } else {
                const int mc = col & 1023;
                const float bv0 = bb[mc], bv1 = bb[mc + 1];
                const float v00 = (c[0] + bv0) * scale, v01 = (c[1] + bv1) * scale;
                const float v10 = (c[2] + bv0) * scale, v11 = (c[3] + bv1) * scale;
                const int hh = mc >> 6, d = mc & 63;
                const int bb0 = row >> 11, t0 = row & 2047;
                const int bb1 = (row + 8) >> 11, t1 = (row + 8) & 2047;
                const size_t i0 = (((size_t)(bb0 * Hh + hh)) * Tq + t0) * Dd + d;
                const size_t i1 = (((size_t)(bb1 * Hh + hh)) * Tq + t1) * Dd + d;
                *(uint32_t*)(dsth + i0) = pack2h(v00, v01);
                *(uint32_t*)(dsth + i1) = pack2h(v10, v11);
            }
        }
    }
}

// ---------------------------------------------------------------------------
// Flash attention, fp16 mma.sync, static softmax — UNCHANGED from round 10
// (best known: 118 us). Round-8 structure + bare ex2 (Q carries 0.125*log2e).
// ---------------------------------------------------------------------------
#define QP 72
#define QTILE (128*QP*2)           // 18432
#define KVARR (64*QP*2)            // 9216
#define OFF_Q 0
#define OFF_KB(s) (QTILE + (s)*2*KVARR)
#define OFF_VB(s) (QTILE + (s)*2*KVARR + KVARR)
#define OFF_MK (QTILE + 6*KVARR)
#define ATT_SMEM_B (OFF_MK + 3*64*4)   // 74496

__global__ __launch_bounds__(256, 2) void attn_h(const int* __restrict__ mask)
{
    extern __shared__ char sm[];
    const uint32_t sb = smem_u32(sm);
    const int tid = threadIdx.x, lane = tid & 31, wid = tid >> 5;
    const int bh = blockIdx.y;
    const int b  = bh >> 4, h = bh & 15;
    const int q0 = blockIdx.x * 128;
    int* Mk = (int*)(sm + OFF_MK);

    // ones columns (V cols 64..71, all 3 buffers) — written once.
    if (tid < 192) {
        const int s = tid >> 6, row = tid & 63;
        uint32_t* p = (uint32_t*)(sm + OFF_VB(s) + (row * QP + 64) * 2);
        p[0] = 0x3C003C00u; p[1] = 0x3C003C00u;
        p[2] = 0x3C003C00u; p[3] = 0x3C003C00u;
    }

    // Q staging: 128 rows, 2 threads/row, 4 cp16 each
    {
        const int qrow = tid >> 1, qcol = (tid & 1) * 32;
        const uint32_t qoff = (uint32_t)(qrow * QP + qcol) * 2;
        const __half* Qg = g_Qh + ((size_t)bh * Tq + q0 + qrow) * Dd + qcol;
#pragma unroll
        for (int j = 0; j < 4; j++)
            cp16(sb + OFF_Q + qoff + j * 16, Qg + j * 8);
        cp_commit();
    }

    // K/V staging coords: 64 rows, 4 threads/row, 2 cp16 per array
    const int krow = tid >> 2, kcol = (tid & 3) * 16;
    const uint32_t koff = (uint32_t)(krow * QP + kcol) * 2;

#define STAGEKV(kt, slot) do {                                                 \
        const __half* Kg_ = g_Kh + ((size_t)bh * Tq + (kt) * 64 + krow) * Dd + kcol; \
        const __half* Vg_ = g_Vh + ((size_t)bh * Tq + (kt) * 64 + krow) * Dd + kcol; \
        cp16(sb + OFF_KB(slot) + koff,      Kg_);                              \
        cp16(sb + OFF_KB(slot) + koff + 16, Kg_ + 8);                          \
        cp16(sb + OFF_VB(slot) + koff,      Vg_);                              \
        cp16(sb + OFF_VB(slot) + koff + 16, Vg_ + 8);                          \
        if (tid < 64) Mk[(slot) * 64 + tid] = mask[b * Tq + (kt) * 64 + tid];  \
        cp_commit();                                                           \
    } while (0)

    STAGEKV(0, 0);
    STAGEKV(1, 1);
    cp_wait<2>();       // Q landed (pending: s0, s1)
    __syncthreads();

    // hoist Q fragments (loop-invariant): warp covers rows wid*16..wid*16+15
    uint32_t qf[4][4];
#pragma unroll
    for (int ks = 0; ks < 4; ks++)
        ldsm4(qf[ks][0], qf[ks][1], qf[ks][2], qf[ks][3],
              sb + OFF_Q +
              ((wid * 16 + (lane & 15)) * QP + ks * 16 + ((lane >> 4) << 3)) * 2);

    float o[8][4];
#pragma unroll
    for (int nt = 0; nt < 8; nt++)
#pragma unroll
        for (int c = 0; c < 4; c++) o[nt][c] = 0.f;
    float ssum[4] = {0.f, 0.f, 0.f, 0.f};   // row-sum fragment (ones-col MMA)

    const int NT = Tq / 64;   // 32
    int r = 0, snext = 2;
    for (int kt = 0; kt < NT; kt++) {
        if (kt < NT - 1) cp_wait<1>(); else cp_wait<0>();
        __syncthreads();   // buffer r ready; also releases slot snext
        if (kt + 2 < NT) {
            STAGEKV(kt + 2, snext);
            snext = (snext == 2) ? 0 : snext + 1;
        }

        // ---- S = Q K^T ----
        float s[8][4];
#pragma unroll
        for (int nt = 0; nt < 8; nt++)
#pragma unroll
            for (int c = 0; c < 4; c++) s[nt][c] = 0.f;

#pragma unroll
        for (int ks = 0; ks < 4; ks++) {
#pragma unroll
            for (int ntp = 0; ntp < 4; ntp++) {
                uint32_t k0, k1, k2, k3;
                ldsm4(k0, k1, k2, k3,
                      sb + OFF_KB(r) +
                      ((ntp * 16 + (lane & 15)) * QP + ks * 16 + ((lane >> 4) << 3)) * 2);
                float* sa = s[2 * ntp];
                float* sc = s[2 * ntp + 1];
                mma_h(sa[0], sa[1], sa[2], sa[3],
                      qf[ks][0], qf[ks][1], qf[ks][2], qf[ks][3], k0, k2);
                mma_h(sc[0], sc[1], sc[2], sc[3],
                      qf[ks][0], qf[ks][1], qf[ks][2], qf[ks][3], k1, k3);
            }
        }

        // ---- mask (warp-uniform all-ones fast path) ----
        const int* mk = Mk + r * 64;
        const bool allone = __all_sync(0xffffffffu,
                (mk[lane] != 0) & (mk[lane + 32] != 0));
        if (!allone) {
            const int c0 = 2 * (lane & 3);
#pragma unroll
            for (int nt = 0; nt < 8; nt++) {
                if (!mk[nt * 8 + c0])     { s[nt][0] = -1e30f; s[nt][2] = -1e30f; }
                if (!mk[nt * 8 + c0 + 1]) { s[nt][1] = -1e30f; s[nt][3] = -1e30f; }
            }
        }

        // ---- static softmax: P = 2^S (Q carries log2e; bare MUFU) ----
#pragma unroll
        for (int nt = 0; nt < 8; nt++) {
            s[nt][0] = ex2f(s[nt][0]);
            s[nt][1] = ex2f(s[nt][1]);
            s[nt][2] = ex2f(s[nt][2]);
            s[nt][3] = ex2f(s[nt][3]);
        }

        // ---- O += P V ; ssum += P @ ones ----
#pragma unroll
        for (int ks = 0; ks < 4; ks++) {
            uint32_t pa0 = pack2h(s[2 * ks][0],     s[2 * ks][1]);
            uint32_t pa1 = pack2h(s[2 * ks][2],     s[2 * ks][3]);
            uint32_t pa2 = pack2h(s[2 * ks + 1][0], s[2 * ks + 1][1]);
            uint32_t pa3 = pack2h(s[2 * ks + 1][2], s[2 * ks + 1][3]);

            uint32_t u0, u1;   // ones-column B fragment (cols 64..71)
            ldsm2t(u0, u1,
                   sb + OFF_VB(r) + ((ks * 16 + (lane & 15)) * QP + 64) * 2);
            mma_h(ssum[0], ssum[1], ssum[2], ssum[3], pa0, pa1, pa2, pa3, u0, u1);

#pragma unroll
            for (int ntp = 0; ntp < 4; ntp++) {
                uint32_t v0, v1, v2, v3;
                ldsm4t(v0, v1, v2, v3,
                       sb + OFF_VB(r) +
                       ((ks * 16 + (lane & 15)) * QP + ntp * 16 + ((lane >> 4) << 3)) * 2);
                float* oa = o[2 * ntp];
                float* ob = o[2 * ntp + 1];
                mma_h(oa[0], oa[1], oa[2], oa[3], pa0, pa1, pa2, pa3, v0, v1);
                mma_h(ob[0], ob[1], ob[2], ob[3], pa0, pa1, pa2, pa3, v2, v3);
            }
        }
        r = (r == 2) ? 0 : r + 1;
    }
#undef STAGEKV

    // ---- finalize: ssum fragment already holds exact row sums ----
    const float inv0 = 1.0f / ssum[0], inv1 = 1.0f / ssum[2];
    const int gr0 = q0 + wid * 16 + (lane >> 2);
#pragma unroll
    for (int nt = 0; nt < 8; nt++) {
        const int col = h * Dd + nt * 8 + 2 * (lane & 3);
        const size_t i0 = ((size_t)b * Tq + gr0) * Cdim + col;
        const size_t i1 = ((size_t)b * Tq + gr0 + 8) * Cdim + col;
        *(uint32_t*)(g_Oh + i0) = pack2h(o[nt][0] * inv0, o[nt][1] * inv0);
        *(uint32_t*)(g_Oh + i1) = pack2h(o[nt][2] * inv1, o[nt][3] * inv1);
    }
}

// ---------------------------------------------------------------------------
extern "C" void kernel_launch(void* const* d_in, const int* in_sizes, int n_in,
                              void* d_out, int out_size)
{
    (void)in_sizes; (void)n_in; (void)out_size;
    const float* x    = (const float*)d_in[0];
    const int*   mask = (const int*)d_in[1];
    const float* Wq = (const float*)d_in[2];
    const float* bq = (const float*)d_in[3];
    const float* Wk = (const float*)d_in[4];
    const float* bk = (const float*)d_in[5];
    const float* Wv = (const float*)d_in[6];
    const float* bv = (const float*)d_in[7];
    const float* Wp = (const float*)d_in[8];
    const float* bp = (const float*)d_in[9];
    float* out = (float*)d_out;

    static bool init = false;
    static __half *xh, *wh, *oh;
    if (!init) {
        cudaFuncSetAttribute(gemm_h,
            cudaFuncAttributeMaxDynamicSharedMemorySize, GEMM_SMEM2);
        cudaFuncSetAttribute(attn_h,
            cudaFuncAttributeMaxDynamicSharedMemorySize, ATT_SMEM_B);
        cudaGetSymbolAddress((void**)&xh, g_xh);
        cudaGetSymbolAddress((void**)&wh, g_Wh);
        cudaGetSymbolAddress((void**)&oh, g_Oh);
        init = true;
    }

    const int NX = Mrows * Cdim;   // 4194304
    const int NW = Cdim * Cdim;    // 1048576
    const size_t WN = (size_t)NW;

    cvt_kernel<<<NX / 2048, 256>>>(x, xh, NX);
    {
        dim3 g(NW / 2048, 4);
        cvt4_kernel<<<g, 256>>>(Wq, Wk, Wv, Wp, wh, NW);
    }

    // fused QKV projection: N = 3072 over packed Wq|Wk|Wv
    {
        dim3 g(3 * Cdim / 128, Mrows / 128);  // (24, 32)
        gemm_h<<<g, 128, GEMM_SMEM2>>>(xh, wh, bq, bk, bv, nullptr, 0);
    }

    {
        dim3 g(Tq / 128, Bsz * Hh);           // (16, 32)
        attn_h<<<g, 256, ATT_SMEM_B>>>(mask);
    }

    // output projection
    {
        dim3 g(Cdim / 128, Mrows / 128);      // (8, 32)
        gemm_h<<<g, 128, GEMM_SMEM2>>>(oh, wh + 3 * WN, bp, bp, bp, out, 1);
    }
}

// round 13
// speedup vs baseline: 1.1868x; 1.1203x over previous
#include <cuda_runtime.h>
#include <cuda_fp16.h>
#include <math.h>
#include <stdint.h>

// Problem constants
#define Bsz 2
#define Tq  2048
#define Cdim 1024
#define Hh  16
#define Dd  64
#define Mrows (Bsz*Tq)   // 4096

// ---------------------------------------------------------------------------
// Device-global scratch (sanctioned no-alloc path)
// ---------------------------------------------------------------------------
__device__ __align__(16) __half g_xh[Mrows*Cdim];
__device__ __align__(16) __half g_Wh[4*Cdim*Cdim];   // Wq,Wk,Wv,Wp packed
__device__ __align__(16) __half g_Qh[Mrows*Cdim];
__device__ __align__(16) __half g_Kh[Mrows*Cdim];
__device__ __align__(16) __half g_Vh[Mrows*Cdim];
__device__ __align__(16) __half g_Oh[Mrows*Cdim];

// ---------------------------------------------------------------------------
// Helpers (family-portable ISA)
// ---------------------------------------------------------------------------
__device__ __forceinline__ uint32_t smem_u32(const void* p) {
    uint32_t a;
    asm("{ .reg .u64 t; cvta.to.shared.u64 t, %1; cvt.u32.u64 %0, t; }"
        : "=r"(a) : "l"(p));
    return a;
}
__device__ __forceinline__ void cp16(uint32_t dst, const void* src) {
    asm volatile("cp.async.cg.shared.global [%0], [%1], 16;"
                 :: "r"(dst), "l"(src));
}
__device__ __forceinline__ void cp_commit() {
    asm volatile("cp.async.commit_group;");
}
template<int N> __device__ __forceinline__ void cp_wait() {
    asm volatile("cp.async.wait_group %0;" :: "n"(N));
}
__device__ __forceinline__ void mma_h(
    float& c0, float& c1, float& c2, float& c3,
    uint32_t a0, uint32_t a1, uint32_t a2, uint32_t a3,
    uint32_t b0, uint32_t b1)
{
    asm volatile(
        "mma.sync.aligned.m16n8k16.row.col.f32.f16.f16.f32 "
        "{%0,%1,%2,%3}, {%4,%5,%6,%7}, {%8,%9}, {%0,%1,%2,%3};"
        : "+f"(c0), "+f"(c1), "+f"(c2), "+f"(c3)
        : "r"(a0), "r"(a1), "r"(a2), "r"(a3), "r"(b0), "r"(b1));
}
__device__ __forceinline__ void ldsm4(
    uint32_t& r0, uint32_t& r1, uint32_t& r2, uint32_t& r3, uint32_t addr)
{
    asm volatile("ldmatrix.sync.aligned.m8n8.x4.shared.b16 {%0,%1,%2,%3}, [%4];"
        : "=r"(r0), "=r"(r1), "=r"(r2), "=r"(r3) : "r"(addr));
}
__device__ __forceinline__ void ldsm4t(
    uint32_t& r0, uint32_t& r1, uint32_t& r2, uint32_t& r3, uint32_t addr)
{
    asm volatile("ldmatrix.sync.aligned.m8n8.x4.trans.shared.b16 {%0,%1,%2,%3}, [%4];"
        : "=r"(r0), "=r"(r1), "=r"(r2), "=r"(r3) : "r"(addr));
}
__device__ __forceinline__ void ldsm2t(uint32_t& r0, uint32_t& r1, uint32_t addr)
{
    asm volatile("ldmatrix.sync.aligned.m8n8.x2.trans.shared.b16 {%0,%1}, [%2];"
        : "=r"(r0), "=r"(r1) : "r"(addr));
}
__device__ __forceinline__ uint32_t pack2h(float lo, float hi) {
    uint32_t r;
    asm("cvt.rn.f16x2.f32 %0, %1, %2;" : "=r"(r) : "f"(hi), "f"(lo));
    return r;
}
__device__ __forceinline__ float ex2f(float x) {
    float r;
    asm("ex2.approx.ftz.f32 %0, %1;" : "=f"(r) : "f"(x));
    return r;
}

// ---------------------------------------------------------------------------
// fused fp32 -> fp16 convert: 8 uniform 1M-element segments.
// y = 0..3 -> quarters of x into g_xh; y = 4..7 -> Wq/Wk/Wv/Wp into g_Wh.
// ---------------------------------------------------------------------------
#define SEG (Cdim*Cdim)   // 1048576

__global__ void cvt_all(const float* __restrict__ x,
                        const float* __restrict__ w0,
                        const float* __restrict__ w1,
                        const float* __restrict__ w2,
                        const float* __restrict__ w3,
                        __half* __restrict__ xh,
                        __half* __restrict__ wh)
{
    const int y = blockIdx.y;
    const float* src;
    __half* dst;
    if (y < 4) { src = x + (size_t)y * SEG;        dst = xh + (size_t)y * SEG; }
    else {
        src = (y == 4) ? w0 : (y == 5) ? w1 : (y == 6) ? w2 : w3;
        dst = wh + (size_t)(y - 4) * SEG;
    }
    int i = (blockIdx.x * blockDim.x + threadIdx.x) * 8;
    float4 a = *(const float4*)(src + i);
    float4 b = *(const float4*)(src + i + 4);
    uint4 o;
    o.x = pack2h(a.x, a.y); o.y = pack2h(a.z, a.w);
    o.z = pack2h(b.x, b.y); o.w = pack2h(b.z, b.w);
    *(uint4*)(dst + i) = o;
}

// ---------------------------------------------------------------------------
// GEMM (round-10 structure: 256 threads, 8 warps 2(m)x4(n), warp tile 64x32,
// BK=64, 3-stage cp.async ring, 2 CTAs/SM = 16 warps). One change: the
// prefetch STG is issued right AFTER the chunk barrier (target slot's
// readers were fenced by this barrier), giving copies a full extra chunk
// of overlap slack.
// mode 0: fused QKV (W [3072,1024]); Q pre-scaled 0.125*log2e.
// mode 1: output projection, fp32 Cout, bias b0.
// ---------------------------------------------------------------------------
#define GP2 72
#define ARR2 (128*GP2*2)           // 18432 bytes per operand array
#define STG2B (2*ARR2)             // 36864 per stage
#define GEMM_SMEM2 (3*STG2B)       // 110592

__global__ __launch_bounds__(256, 2) void gemm_h(
    const __half* __restrict__ A, const __half* __restrict__ W,
    const float* __restrict__ b0, const float* __restrict__ b1,
    const float* __restrict__ b2, float* __restrict__ Cout, int mode)
{
    extern __shared__ char sm[];
    const uint32_t sb = smem_u32(sm);
    const int tid = threadIdx.x, lane = tid & 31, wid = tid >> 5;
    const int wm = wid & 1, wn = wid >> 1;
    const int m0 = blockIdx.y * 128, n0 = blockIdx.x * 128;

    const int srow = tid >> 1, scol = (tid & 1) * 32;
    const uint32_t soff = (uint32_t)(srow * GP2 + scol) * 2;
    const __half* Ar = A + (size_t)(m0 + srow) * Cdim + scol;
    const __half* Wr = W + (size_t)(n0 + srow) * Cdim + scol;

#define STG(kc, slot) do {                                        \
        uint32_t st_ = sb + (slot) * STG2B;                       \
        cp16(st_ + soff,               Ar + (kc));                \
        cp16(st_ + soff + 16,          Ar + (kc) + 8);            \
        cp16(st_ + soff + 32,          Ar + (kc) + 16);           \
        cp16(st_ + soff + 48,          Ar + (kc) + 24);           \
        cp16(st_ + ARR2 + soff,        Wr + (kc));                \
        cp16(st_ + ARR2 + soff + 16,   Wr + (kc) + 8);            \
        cp16(st_ + ARR2 + soff + 32,   Wr + (kc) + 16);           \
        cp16(st_ + ARR2 + soff + 48,   Wr + (kc) + 24);           \
        cp_commit();                                              \
    } while (0)

    float acc[4][4][4];
#pragma unroll
    for (int a = 0; a < 4; a++)
#pragma unroll
        for (int b = 0; b < 4; b++)
#pragma unroll
            for (int c = 0; c < 4; c++) acc[a][b][c] = 0.f;

    STG(0, 0); STG(64, 1);

    int slot_next = 2;
    for (int kt = 0; kt < 16; kt++) {
        if (kt < 15) cp_wait<1>(); else cp_wait<0>();
        __syncthreads();               // chunk kt resident; slot_next free
        if (kt + 2 < 16) {             // prefetch hoisted before compute
            STG((kt + 2) * 64, slot_next);
            slot_next = (slot_next == 2) ? 0 : slot_next + 1;
        }

        const int sl = kt - (kt / 3) * 3;   // kt mod 3
        const uint32_t stb = sb + sl * STG2B;

#pragma unroll
        for (int s = 0; s < 4; s++) {
            const uint32_t cg = s * 16 + ((lane >> 4) << 3);
            uint32_t bf[2][4], af[4][4];
#pragma unroll
            for (int ntp = 0; ntp < 2; ntp++)
                ldsm4(bf[ntp][0], bf[ntp][1], bf[ntp][2], bf[ntp][3],
                      stb + ARR2 +
                      ((wn * 32 + ntp * 16 + (lane & 15)) * GP2 + cg) * 2);
#pragma unroll
            for (int mt = 0; mt < 4; mt++)
                ldsm4(af[mt][0], af[mt][1], af[mt][2], af[mt][3],
                      stb + ((wm * 64 + mt * 16 + (lane & 15)) * GP2 + cg) * 2);
#pragma unroll
            for (int mt = 0; mt < 4; mt++)
#pragma unroll
                for (int nt = 0; nt < 4; nt++) {
                    float* c = acc[mt][nt];
                    mma_h(c[0], c[1], c[2], c[3],
                          af[mt][0], af[mt][1], af[mt][2], af[mt][3],
                          bf[nt >> 1][nt & 1], bf[nt >> 1][(nt & 1) + 2]);
                }
        }
    }
#undef STG

    // epilogue
    const int mat = n0 >> 10;  // constant per CTA (mode 0)
    const float* bb = (mat == 0) ? b0 : (mat == 1) ? b1 : b2;
    __half* dsth = (mat == 0) ? g_Qh : (mat == 1) ? g_Kh : g_Vh;
    // Q scale folds 1/sqrt(D) AND log2(e) so attention uses ex2 directly
    const float scale = (mat == 0) ? 0.125f * 1.4426950408889634f : 1.0f;

#pragma unroll
    for (int mt = 0; mt < 4; mt++) {
#pragma unroll
        for (int nt = 0; nt < 4; nt++) {
            float* c = acc[mt][nt];
            const int row = m0 + wm * 64 + mt * 16 + (lane >> 2);
            const int col = n0 + wn * 32 + nt * 8 + 2 * (lane & 3);
            if (mode == 1) {
                const float bv0 = b0[col], bv1 = b0[col + 1];
                *(float2*)(Cout + (size_t)row * Cdim + col) =
                    make_float2(c[0] + bv0, c[1] + bv1);
                *(float2*)(Cout + (size_t)(row + 8) * Cdim + col) =
                    make_float2(c[2] + bv0, c[3] + bv1);
            } else {
                const int mc = col & 1023;
                const float bv0 = bb[mc], bv1 = bb[mc + 1];
                const float v00 = (c[0] + bv0) * scale, v01 = (c[1] + bv1) * scale;
                const float v10 = (c[2] + bv0) * scale, v11 = (c[3] + bv1) * scale;
                const int hh = mc >> 6, d = mc & 63;
                const int bb0 = row >> 11, t0 = row & 2047;
                const int bb1 = (row + 8) >> 11, t1 = (row + 8) & 2047;
                const size_t i0 = (((size_t)(bb0 * Hh + hh)) * Tq + t0) * Dd + d;
                const size_t i1 = (((size_t)(bb1 * Hh + hh)) * Tq + t1) * Dd + d;
                *(uint32_t*)(dsth + i0) = pack2h(v00, v01);
                *(uint32_t*)(dsth + i1) = pack2h(v10, v11);
            }
        }
    }
}

// ---------------------------------------------------------------------------
// Flash attention, fp16 mma.sync, static softmax — UNCHANGED from round 10
// (best known: 118 us). Round-8 structure + bare ex2 (Q carries 0.125*log2e).
// ---------------------------------------------------------------------------
#define QP 72
#define QTILE (128*QP*2)           // 18432
#define KVARR (64*QP*2)            // 9216
#define OFF_Q 0
#define OFF_KB(s) (QTILE + (s)*2*KVARR)
#define OFF_VB(s) (QTILE + (s)*2*KVARR + KVARR)
#define OFF_MK (QTILE + 6*KVARR)
#define ATT_SMEM_B (OFF_MK + 3*64*4)   // 74496

__global__ __launch_bounds__(256, 2) void attn_h(const int* __restrict__ mask)
{
    extern __shared__ char sm[];
    const uint32_t sb = smem_u32(sm);
    const int tid = threadIdx.x, lane = tid & 31, wid = tid >> 5;
    const int bh = blockIdx.y;
    const int b  = bh >> 4, h = bh & 15;
    const int q0 = blockIdx.x * 128;
    int* Mk = (int*)(sm + OFF_MK);

    // ones columns (V cols 64..71, all 3 buffers) — written once.
    if (tid < 192) {
        const int s = tid >> 6, row = tid & 63;
        uint32_t* p = (uint32_t*)(sm + OFF_VB(s) + (row * QP + 64) * 2);
        p[0] = 0x3C003C00u; p[1] = 0x3C003C00u;
        p[2] = 0x3C003C00u; p[3] = 0x3C003C00u;
    }

    // Q staging: 128 rows, 2 threads/row, 4 cp16 each
    {
        const int qrow = tid >> 1, qcol = (tid & 1) * 32;
        const uint32_t qoff = (uint32_t)(qrow * QP + qcol) * 2;
        const __half* Qg = g_Qh + ((size_t)bh * Tq + q0 + qrow) * Dd + qcol;
#pragma unroll
        for (int j = 0; j < 4; j++)
            cp16(sb + OFF_Q + qoff + j * 16, Qg + j * 8);
        cp_commit();
    }

    // K/V staging coords: 64 rows, 4 threads/row, 2 cp16 per array
    const int krow = tid >> 2, kcol = (tid & 3) * 16;
    const uint32_t koff = (uint32_t)(krow * QP + kcol) * 2;

#define STAGEKV(kt, slot) do {                                                 \
        const __half* Kg_ = g_Kh + ((size_t)bh * Tq + (kt) * 64 + krow) * Dd + kcol; \
        const __half* Vg_ = g_Vh + ((size_t)bh * Tq + (kt) * 64 + krow) * Dd + kcol; \
        cp16(sb + OFF_KB(slot) + koff,      Kg_);                              \
        cp16(sb + OFF_KB(slot) + koff + 16, Kg_ + 8);                          \
        cp16(sb + OFF_VB(slot) + koff,      Vg_);                              \
        cp16(sb + OFF_VB(slot) + koff + 16, Vg_ + 8);                          \
        if (tid < 64) Mk[(slot) * 64 + tid] = mask[b * Tq + (kt) * 64 + tid];  \
        cp_commit();                                                           \
    } while (0)

    STAGEKV(0, 0);
    STAGEKV(1, 1);
    cp_wait<2>();       // Q landed (pending: s0, s1)
    __syncthreads();

    // hoist Q fragments (loop-invariant): warp covers rows wid*16..wid*16+15
    uint32_t qf[4][4];
#pragma unroll
    for (int ks = 0; ks < 4; ks++)
        ldsm4(qf[ks][0], qf[ks][1], qf[ks][2], qf[ks][3],
              sb + OFF_Q +
              ((wid * 16 + (lane & 15)) * QP + ks * 16 + ((lane >> 4) << 3)) * 2);

    float o[8][4];
#pragma unroll
    for (int nt = 0; nt < 8; nt++)
#pragma unroll
        for (int c = 0; c < 4; c++) o[nt][c] = 0.f;
    float ssum[4] = {0.f, 0.f, 0.f, 0.f};   // row-sum fragment (ones-col MMA)

    const int NT = Tq / 64;   // 32
    int r = 0, snext = 2;
    for (int kt = 0; kt < NT; kt++) {
        if (kt < NT - 1) cp_wait<1>(); else cp_wait<0>();
        __syncthreads();   // buffer r ready; also releases slot snext
        if (kt + 2 < NT) {
            STAGEKV(kt + 2, snext);
            snext = (snext == 2) ? 0 : snext + 1;
        }

        // ---- S = Q K^T ----
        float s[8][4];
#pragma unroll
        for (int nt = 0; nt < 8; nt++)
#pragma unroll
            for (int c = 0; c < 4; c++) s[nt][c] = 0.f;

#pragma unroll
        for (int ks = 0; ks < 4; ks++) {
#pragma unroll
            for (int ntp = 0; ntp < 4; ntp++) {
                uint32_t k0, k1, k2, k3;
                ldsm4(k0, k1, k2, k3,
                      sb + OFF_KB(r) +
                      ((ntp * 16 + (lane & 15)) * QP + ks * 16 + ((lane >> 4) << 3)) * 2);
                float* sa = s[2 * ntp];
                float* sc = s[2 * ntp + 1];
                mma_h(sa[0], sa[1], sa[2], sa[3],
                      qf[ks][0], qf[ks][1], qf[ks][2], qf[ks][3], k0, k2);
                mma_h(sc[0], sc[1], sc[2], sc[3],
                      qf[ks][0], qf[ks][1], qf[ks][2], qf[ks][3], k1, k3);
            }
        }

        // ---- mask (warp-uniform all-ones fast path) ----
        const int* mk = Mk + r * 64;
        const bool allone = __all_sync(0xffffffffu,
                (mk[lane] != 0) & (mk[lane + 32] != 0));
        if (!allone) {
            const int c0 = 2 * (lane & 3);
#pragma unroll
            for (int nt = 0; nt < 8; nt++) {
                if (!mk[nt * 8 + c0])     { s[nt][0] = -1e30f; s[nt][2] = -1e30f; }
                if (!mk[nt * 8 + c0 + 1]) { s[nt][1] = -1e30f; s[nt][3] = -1e30f; }
            }
        }

        // ---- static softmax: P = 2^S (Q carries log2e; bare MUFU) ----
#pragma unroll
        for (int nt = 0; nt < 8; nt++) {
            s[nt][0] = ex2f(s[nt][0]);
            s[nt][1] = ex2f(s[nt][1]);
            s[nt][2] = ex2f(s[nt][2]);
            s[nt][3] = ex2f(s[nt][3]);
        }

        // ---- O += P V ; ssum += P @ ones ----
#pragma unroll
        for (int ks = 0; ks < 4; ks++) {
            uint32_t pa0 = pack2h(s[2 * ks][0],     s[2 * ks][1]);
            uint32_t pa1 = pack2h(s[2 * ks][2],     s[2 * ks][3]);
            uint32_t pa2 = pack2h(s[2 * ks + 1][0], s[2 * ks + 1][1]);
            uint32_t pa3 = pack2h(s[2 * ks + 1][2], s[2 * ks + 1][3]);

            uint32_t u0, u1;   // ones-column B fragment (cols 64..71)
            ldsm2t(u0, u1,
                   sb + OFF_VB(r) + ((ks * 16 + (lane & 15)) * QP + 64) * 2);
            mma_h(ssum[0], ssum[1], ssum[2], ssum[3], pa0, pa1, pa2, pa3, u0, u1);

#pragma unroll
            for (int ntp = 0; ntp < 4; ntp++) {
                uint32_t v0, v1, v2, v3;
                ldsm4t(v0, v1, v2, v3,
                       sb + OFF_VB(r) +
                       ((ks * 16 + (lane & 15)) * QP + ntp * 16 + ((lane >> 4) << 3)) * 2);
                float* oa = o[2 * ntp];
                float* ob = o[2 * ntp + 1];
                mma_h(oa[0], oa[1], oa[2], oa[3], pa0, pa1, pa2, pa3, v0, v1);
                mma_h(ob[0], ob[1], ob[2], ob[3], pa0, pa1, pa2, pa3, v2, v3);
            }
        }
        r = (r == 2) ? 0 : r + 1;
    }
#undef STAGEKV

    // ---- finalize: ssum fragment already holds exact row sums ----
    const float inv0 = 1.0f / ssum[0], inv1 = 1.0f / ssum[2];
    const int gr0 = q0 + wid * 16 + (lane >> 2);
#pragma unroll
    for (int nt = 0; nt < 8; nt++) {
        const int col = h * Dd + nt * 8 + 2 * (lane & 3);
        const size_t i0 = ((size_t)b * Tq + gr0) * Cdim + col;
        const size_t i1 = ((size_t)b * Tq + gr0 + 8) * Cdim + col;
        *(uint32_t*)(g_Oh + i0) = pack2h(o[nt][0] * inv0, o[nt][1] * inv0);
        *(uint32_t*)(g_Oh + i1) = pack2h(o[nt][2] * inv1, o[nt][3] * inv1);
    }
}

// ---------------------------------------------------------------------------
extern "C" void kernel_launch(void* const* d_in, const int* in_sizes, int n_in,
                              void* d_out, int out_size)
{
    (void)in_sizes; (void)n_in; (void)out_size;
    const float* x    = (const float*)d_in[0];
    const int*   mask = (const int*)d_in[1];
    const float* Wq = (const float*)d_in[2];
    const float* bq = (const float*)d_in[3];
    const float* Wk = (const float*)d_in[4];
    const float* bk = (const float*)d_in[5];
    const float* Wv = (const float*)d_in[6];
    const float* bv = (const float*)d_in[7];
    const float* Wp = (const float*)d_in[8];
    const float* bp = (const float*)d_in[9];
    float* out = (float*)d_out;

    static bool init = false;
    static __half *xh, *wh, *oh;
    if (!init) {
        cudaFuncSetAttribute(gemm_h,
            cudaFuncAttributeMaxDynamicSharedMemorySize, GEMM_SMEM2);
        cudaFuncSetAttribute(attn_h,
            cudaFuncAttributeMaxDynamicSharedMemorySize, ATT_SMEM_B);
        cudaGetSymbolAddress((void**)&xh, g_xh);
        cudaGetSymbolAddress((void**)&wh, g_Wh);
        cudaGetSymbolAddress((void**)&oh, g_Oh);
        init = true;
    }

    const size_t WN = (size_t)SEG;   // 1048576

    // single fused convert launch: 8 segments x 1M elements
    {
        dim3 g(SEG / 2048, 8);
        cvt_all<<<g, 256>>>(x, Wq, Wk, Wv, Wp, xh, wh);
    }

    // fused QKV projection: N = 3072 over packed Wq|Wk|Wv
    {
        dim3 g(3 * Cdim / 128, Mrows / 128);  // (24, 32)
        gemm_h<<<g, 256, GEMM_SMEM2>>>(xh, wh, bq, bk, bv, nullptr, 0);
    }

    {
        dim3 g(Tq / 128, Bsz * Hh);           // (16, 32)
        attn_h<<<g, 256, ATT_SMEM_B>>>(mask);
    }

    // output projection
    {
        dim3 g(Cdim / 128, Mrows / 128);      // (8, 32)
        gemm_h<<<g, 256, GEMM_SMEM2>>>(oh, wh + 3 * WN, bp, bp, bp, out, 1);
    }
}

// round 14
// speedup vs baseline: 1.1961x; 1.0078x over previous
#include <cuda_runtime.h>
#include <cuda_fp16.h>
#include <math.h>
#include <stdint.h>

// Problem constants
#define Bsz 2
#define Tq  2048
#define Cdim 1024
#define Hh  16
#define Dd  64
#define Mrows (Bsz*Tq)   // 4096

// ---------------------------------------------------------------------------
// Device-global scratch (sanctioned no-alloc path)
// ---------------------------------------------------------------------------
__device__ __align__(16) __half g_xh[Mrows*Cdim];
__device__ __align__(16) __half g_Wh[4*Cdim*Cdim];   // Wq,Wk,Wv,Wp packed
__device__ __align__(16) __half g_Qh[Mrows*Cdim];
__device__ __align__(16) __half g_Kh[Mrows*Cdim];
__device__ __align__(16) __half g_Vh[Mrows*Cdim];
__device__ __align__(16) __half g_Oh[Mrows*Cdim];

// ---------------------------------------------------------------------------
// Helpers (family-portable ISA)
// ---------------------------------------------------------------------------
__device__ __forceinline__ uint32_t smem_u32(const void* p) {
    uint32_t a;
    asm("{ .reg .u64 t; cvta.to.shared.u64 t, %1; cvt.u32.u64 %0, t; }"
        : "=r"(a) : "l"(p));
    return a;
}
__device__ __forceinline__ void cp16(uint32_t dst, const void* src) {
    asm volatile("cp.async.cg.shared.global [%0], [%1], 16;"
                 :: "r"(dst), "l"(src));
}
__device__ __forceinline__ void cp_commit() {
    asm volatile("cp.async.commit_group;");
}
template<int N> __device__ __forceinline__ void cp_wait() {
    asm volatile("cp.async.wait_group %0;" :: "n"(N));
}
__device__ __forceinline__ void mma_h(
    float& c0, float& c1, float& c2, float& c3,
    uint32_t a0, uint32_t a1, uint32_t a2, uint32_t a3,
    uint32_t b0, uint32_t b1)
{
    asm volatile(
        "mma.sync.aligned.m16n8k16.row.col.f32.f16.f16.f32 "
        "{%0,%1,%2,%3}, {%4,%5,%6,%7}, {%8,%9}, {%0,%1,%2,%3};"
        : "+f"(c0), "+f"(c1), "+f"(c2), "+f"(c3)
        : "r"(a0), "r"(a1), "r"(a2), "r"(a3), "r"(b0), "r"(b1));
}
__device__ __forceinline__ void ldsm4(
    uint32_t& r0, uint32_t& r1, uint32_t& r2, uint32_t& r3, uint32_t addr)
{
    asm volatile("ldmatrix.sync.aligned.m8n8.x4.shared.b16 {%0,%1,%2,%3}, [%4];"
        : "=r"(r0), "=r"(r1), "=r"(r2), "=r"(r3) : "r"(addr));
}
__device__ __forceinline__ void ldsm4t(
    uint32_t& r0, uint32_t& r1, uint32_t& r2, uint32_t& r3, uint32_t addr)
{
    asm volatile("ldmatrix.sync.aligned.m8n8.x4.trans.shared.b16 {%0,%1,%2,%3}, [%4];"
        : "=r"(r0), "=r"(r1), "=r"(r2), "=r"(r3) : "r"(addr));
}
__device__ __forceinline__ void ldsm2t(uint32_t& r0, uint32_t& r1, uint32_t addr)
{
    asm volatile("ldmatrix.sync.aligned.m8n8.x2.trans.shared.b16 {%0,%1}, [%2];"
        : "=r"(r0), "=r"(r1) : "r"(addr));
}
__device__ __forceinline__ uint32_t pack2h(float lo, float hi) {
    uint32_t r;
    asm("cvt.rn.f16x2.f32 %0, %1, %2;" : "=r"(r) : "f"(hi), "f"(lo));
    return r;
}
__device__ __forceinline__ float ex2f(float x) {
    float r;
    asm("ex2.approx.ftz.f32 %0, %1;" : "=f"(r) : "f"(x));
    return r;
}

// ---------------------------------------------------------------------------
// fp32 -> fp16 converts (round-10 versions)
// ---------------------------------------------------------------------------
__global__ void cvt_kernel(const float* __restrict__ src,
                           __half* __restrict__ dst, int n)
{
    int i = (blockIdx.x * blockDim.x + threadIdx.x) * 8;
    if (i >= n) return;
    float4 a = *(const float4*)(src + i);
    float4 b = *(const float4*)(src + i + 4);
    uint4 o;
    o.x = pack2h(a.x, a.y); o.y = pack2h(a.z, a.w);
    o.z = pack2h(b.x, b.y); o.w = pack2h(b.z, b.w);
    *(uint4*)(dst + i) = o;
}

__global__ void cvt4_kernel(const float* __restrict__ s0,
                            const float* __restrict__ s1,
                            const float* __restrict__ s2,
                            const float* __restrict__ s3,
                            __half* __restrict__ dst, int n)
{
    const float* s = (blockIdx.y == 0) ? s0 : (blockIdx.y == 1) ? s1
                   : (blockIdx.y == 2) ? s2 : s3;
    int i = (blockIdx.x * blockDim.x + threadIdx.x) * 8;
    if (i >= n) return;
    const size_t off = (size_t)blockIdx.y * n;
    float4 a = *(const float4*)(s + i);
    float4 b = *(const float4*)(s + i + 4);
    uint4 o;
    o.x = pack2h(a.x, a.y); o.y = pack2h(a.z, a.w);
    o.z = pack2h(b.x, b.y); o.w = pack2h(b.z, b.w);
    *(uint4*)(dst + off + i) = o;
}

// ---------------------------------------------------------------------------
// GEMM — EXACT round-10 structure (proven best: QKV 131us, outproj 44us).
// 256 threads, 8 warps 2(m)x4(n), warp tile 64x32, BK=64, 3-stage ring,
// prefetch issued AFTER compute, 2 CTAs/SM = 16 warps.
// mode 0: fused QKV (W [3072,1024]); Q pre-scaled 0.125*log2e.
// mode 1: output projection, fp32 Cout, bias b0.
// ---------------------------------------------------------------------------
#define GP2 72
#define ARR2 (128*GP2*2)           // 18432 bytes per operand array
#define STG2B (2*ARR2)             // 36864 per stage
#define GEMM_SMEM2 (3*STG2B)       // 110592

__global__ __launch_bounds__(256, 2) void gemm_h(
    const __half* __restrict__ A, const __half* __restrict__ W,
    const float* __restrict__ b0, const float* __restrict__ b1,
    const float* __restrict__ b2, float* __restrict__ Cout, int mode)
{
    extern __shared__ char sm[];
    const uint32_t sb = smem_u32(sm);
    const int tid = threadIdx.x, lane = tid & 31, wid = tid >> 5;
    const int wm = wid & 1, wn = wid >> 1;
    const int m0 = blockIdx.y * 128, n0 = blockIdx.x * 128;

    const int srow = tid >> 1, scol = (tid & 1) * 32;
    const uint32_t soff = (uint32_t)(srow * GP2 + scol) * 2;
    const __half* Ar = A + (size_t)(m0 + srow) * Cdim + scol;
    const __half* Wr = W + (size_t)(n0 + srow) * Cdim + scol;

#define STG(kc, slot) do {                                        \
        uint32_t st_ = sb + (slot) * STG2B;                       \
        cp16(st_ + soff,               Ar + (kc));                \
        cp16(st_ + soff + 16,          Ar + (kc) + 8);            \
        cp16(st_ + soff + 32,          Ar + (kc) + 16);           \
        cp16(st_ + soff + 48,          Ar + (kc) + 24);           \
        cp16(st_ + ARR2 + soff,        Wr + (kc));                \
        cp16(st_ + ARR2 + soff + 16,   Wr + (kc) + 8);            \
        cp16(st_ + ARR2 + soff + 32,   Wr + (kc) + 16);           \
        cp16(st_ + ARR2 + soff + 48,   Wr + (kc) + 24);           \
        cp_commit();                                              \
    } while (0)

    float acc[4][4][4];
#pragma unroll
    for (int a = 0; a < 4; a++)
#pragma unroll
        for (int b = 0; b < 4; b++)
#pragma unroll
            for (int c = 0; c < 4; c++) acc[a][b][c] = 0.f;

    STG(0, 0); STG(64, 1);

    int slot_next = 2;
    for (int kt = 0; kt < 16; kt++) {
        if (kt < 14) cp_wait<1>(); else cp_wait<0>();
        __syncthreads();

        const int sl = kt - (kt / 3) * 3;   // kt mod 3
        const uint32_t stb = sb + sl * STG2B;

#pragma unroll
        for (int s = 0; s < 4; s++) {
            const uint32_t cg = s * 16 + ((lane >> 4) << 3);
            uint32_t bf[2][4], af[4][4];
#pragma unroll
            for (int ntp = 0; ntp < 2; ntp++)
                ldsm4(bf[ntp][0], bf[ntp][1], bf[ntp][2], bf[ntp][3],
                      stb + ARR2 +
                      ((wn * 32 + ntp * 16 + (lane & 15)) * GP2 + cg) * 2);
#pragma unroll
            for (int mt = 0; mt < 4; mt++)
                ldsm4(af[mt][0], af[mt][1], af[mt][2], af[mt][3],
                      stb + ((wm * 64 + mt * 16 + (lane & 15)) * GP2 + cg) * 2);
#pragma unroll
            for (int mt = 0; mt < 4; mt++)
#pragma unroll
                for (int nt = 0; nt < 4; nt++) {
                    float* c = acc[mt][nt];
                    mma_h(c[0], c[1], c[2], c[3],
                          af[mt][0], af[mt][1], af[mt][2], af[mt][3],
                          bf[nt >> 1][nt & 1], bf[nt >> 1][(nt & 1) + 2]);
                }
        }
        if (kt + 2 < 16) {
            STG((kt + 2) * 64, slot_next);
            slot_next = (slot_next == 2) ? 0 : slot_next + 1;
        }
    }
#undef STG

    // epilogue
    const int mat = n0 >> 10;  // constant per CTA (mode 0)
    const float* bb = (mat == 0) ? b0 : (mat == 1) ? b1 : b2;
    __half* dsth = (mat == 0) ? g_Qh : (mat == 1) ? g_Kh : g_Vh;
    // Q scale folds 1/sqrt(D) AND log2(e) so attention uses ex2 directly
    const float scale = (mat == 0) ? 0.125f * 1.4426950408889634f : 1.0f;

#pragma unroll
    for (int mt = 0; mt < 4; mt++) {
#pragma unroll
        for (int nt = 0; nt < 4; nt++) {
            float* c = acc[mt][nt];
            const int row = m0 + wm * 64 + mt * 16 + (lane >> 2);
            const int col = n0 + wn * 32 + nt * 8 + 2 * (lane & 3);
            if (mode == 1) {
                const float bv0 = b0[col], bv1 = b0[col + 1];
                *(float2*)(Cout + (size_t)row * Cdim + col) =
                    make_float2(c[0] + bv0, c[1] + bv1);
                *(float2*)(Cout + (size_t)(row + 8) * Cdim + col) =
                    make_float2(c[2] + bv0, c[3] + bv1);
            } else {
                const int mc = col & 1023;
                const float bv0 = bb[mc], bv1 = bb[mc + 1];
                const float v00 = (c[0] + bv0) * scale, v01 = (c[1] + bv1) * scale;
                const float v10 = (c[2] + bv0) * scale, v11 = (c[3] + bv1) * scale;
                const int hh = mc >> 6, d = mc & 63;
                const int bb0 = row >> 11, t0 = row & 2047;
                const int bb1 = (row + 8) >> 11, t1 = (row + 8) & 2047;
                const size_t i0 = (((size_t)(bb0 * Hh + hh)) * Tq + t0) * Dd + d;
                const size_t i1 = (((size_t)(bb1 * Hh + hh)) * Tq + t1) * Dd + d;
                *(uint32_t*)(dsth + i0) = pack2h(v00, v01);
                *(uint32_t*)(dsth + i1) = pack2h(v10, v11);
            }
        }
    }
}

// ---------------------------------------------------------------------------
// Flash attention, fp16 mma.sync, static softmax. NEW: q-tile 256 (two
// 128-query halves processed sequentially against each staged K/V tile) —
// halves cp.async ops per query, which round-13 analysis identified as the
// binding resource (LDGSTS issue rate 8 cyc/op/SMSP). K/V and Q fragments
// are re-loaded from smem per half (LDSM is cheap; cp-issue is not).
// 3-buffer K/V ring, 1 barrier/tile, ones-column row sums, mask fast path.
// 256 threads (8 warps), occupancy 1 (regs ~150).
// ---------------------------------------------------------------------------
#define QP 72
#define QTILE2 (256*QP*2)          // 36864
#define KVARR (64*QP*2)            // 9216
#define OFF_Q 0
#define OFF_KB(s) (QTILE2 + (s)*2*KVARR)
#define OFF_VB(s) (QTILE2 + (s)*2*KVARR + KVARR)
#define OFF_MK (QTILE2 + 6*KVARR)
#define ATT_SMEM_B (OFF_MK + 3*64*4)   // 92928

__global__ __launch_bounds__(256, 1) void attn_h(const int* __restrict__ mask)
{
    extern __shared__ char sm[];
    const uint32_t sb = smem_u32(sm);
    const int tid = threadIdx.x, lane = tid & 31, wid = tid >> 5;
    const int bh = blockIdx.y;
    const int b  = bh >> 4, h = bh & 15;
    const int q0 = blockIdx.x * 256;
    int* Mk = (int*)(sm + OFF_MK);

    // ones columns (V cols 64..71, all 3 buffers) — written once.
    if (tid < 192) {
        const int s = tid >> 6, row = tid & 63;
        uint32_t* p = (uint32_t*)(sm + OFF_VB(s) + (row * QP + 64) * 2);
        p[0] = 0x3C003C00u; p[1] = 0x3C003C00u;
        p[2] = 0x3C003C00u; p[3] = 0x3C003C00u;
    }

    // Q staging: 256 rows, 1 thread/row, 8 cp16 each
    {
        const uint32_t qoff = (uint32_t)(tid * QP) * 2;
        const __half* Qg = g_Qh + ((size_t)bh * Tq + q0 + tid) * Dd;
#pragma unroll
        for (int j = 0; j < 8; j++)
            cp16(sb + OFF_Q + qoff + j * 16, Qg + j * 8);
        cp_commit();
    }

    // K/V staging coords: 64 rows, 4 threads/row, 2 cp16 per array
    const int krow = tid >> 2, kcol = (tid & 3) * 16;
    const uint32_t koff = (uint32_t)(krow * QP + kcol) * 2;

#define STAGEKV(kt, slot) do {                                                 \
        const __half* Kg_ = g_Kh + ((size_t)bh * Tq + (kt) * 64 + krow) * Dd + kcol; \
        const __half* Vg_ = g_Vh + ((size_t)bh * Tq + (kt) * 64 + krow) * Dd + kcol; \
        cp16(sb + OFF_KB(slot) + koff,      Kg_);                              \
        cp16(sb + OFF_KB(slot) + koff + 16, Kg_ + 8);                          \
        cp16(sb + OFF_VB(slot) + koff,      Vg_);                              \
        cp16(sb + OFF_VB(slot) + koff + 16, Vg_ + 8);                          \
        if (tid < 64) Mk[(slot) * 64 + tid] = mask[b * Tq + (kt) * 64 + tid];  \
        cp_commit();                                                           \
    } while (0)

    STAGEKV(0, 0);
    STAGEKV(1, 1);
    cp_wait<2>();       // Q landed (pending: s0, s1)
    __syncthreads();

    float o[2][8][4];
#pragma unroll
    for (int hf = 0; hf < 2; hf++)
#pragma unroll
        for (int nt = 0; nt < 8; nt++)
#pragma unroll
            for (int c = 0; c < 4; c++) o[hf][nt][c] = 0.f;
    float ssum[2][4] = {{0.f, 0.f, 0.f, 0.f}, {0.f, 0.f, 0.f, 0.f}};

    const int NT = Tq / 64;   // 32
    int r = 0, snext = 2;
    for (int kt = 0; kt < NT; kt++) {
        if (kt < NT - 1) cp_wait<1>(); else cp_wait<0>();
        __syncthreads();   // buffer r ready; also releases slot snext
        if (kt + 2 < NT) {
            STAGEKV(kt + 2, snext);
            snext = (snext == 2) ? 0 : snext + 1;
        }

        // mask fast-path flag (shared by both halves)
        const int* mk = Mk + r * 64;
        const bool allone = __all_sync(0xffffffffu,
                (mk[lane] != 0) & (mk[lane + 32] != 0));

#pragma unroll
        for (int hf = 0; hf < 2; hf++) {
            // Q fragments for this half (re-loaded from smem; LDSM is cheap)
            uint32_t qf[4][4];
#pragma unroll
            for (int ks = 0; ks < 4; ks++)
                ldsm4(qf[ks][0], qf[ks][1], qf[ks][2], qf[ks][3],
                      sb + OFF_Q +
                      ((hf * 128 + wid * 16 + (lane & 15)) * QP + ks * 16 +
                       ((lane >> 4) << 3)) * 2);

            // ---- S = Q K^T ----
            float s[8][4];
#pragma unroll
            for (int nt = 0; nt < 8; nt++)
#pragma unroll
                for (int c = 0; c < 4; c++) s[nt][c] = 0.f;

#pragma unroll
            for (int ks = 0; ks < 4; ks++) {
#pragma unroll
                for (int ntp = 0; ntp < 4; ntp++) {
                    uint32_t k0, k1, k2, k3;
                    ldsm4(k0, k1, k2, k3,
                          sb + OFF_KB(r) +
                          ((ntp * 16 + (lane & 15)) * QP + ks * 16 +
                           ((lane >> 4) << 3)) * 2);
                    float* sa = s[2 * ntp];
                    float* sc = s[2 * ntp + 1];
                    mma_h(sa[0], sa[1], sa[2], sa[3],
                          qf[ks][0], qf[ks][1], qf[ks][2], qf[ks][3], k0, k2);
                    mma_h(sc[0], sc[1], sc[2], sc[3],
                          qf[ks][0], qf[ks][1], qf[ks][2], qf[ks][3], k1, k3);
                }
            }

            // ---- mask ----
            if (!allone) {
                const int c0 = 2 * (lane & 3);
#pragma unroll
                for (int nt = 0; nt < 8; nt++) {
                    if (!mk[nt * 8 + c0])     { s[nt][0] = -1e30f; s[nt][2] = -1e30f; }
                    if (!mk[nt * 8 + c0 + 1]) { s[nt][1] = -1e30f; s[nt][3] = -1e30f; }
                }
            }

            // ---- static softmax: P = 2^S ----
#pragma unroll
            for (int nt = 0; nt < 8; nt++) {
                s[nt][0] = ex2f(s[nt][0]);
                s[nt][1] = ex2f(s[nt][1]);
                s[nt][2] = ex2f(s[nt][2]);
                s[nt][3] = ex2f(s[nt][3]);
            }

            // ---- O += P V ; ssum += P @ ones ----
#pragma unroll
            for (int ks = 0; ks < 4; ks++) {
                uint32_t pa0 = pack2h(s[2 * ks][0],     s[2 * ks][1]);
                uint32_t pa1 = pack2h(s[2 * ks][2],     s[2 * ks][3]);
                uint32_t pa2 = pack2h(s[2 * ks + 1][0], s[2 * ks + 1][1]);
                uint32_t pa3 = pack2h(s[2 * ks + 1][2], s[2 * ks + 1][3]);

                uint32_t u0, u1;   // ones-column B fragment
                ldsm2t(u0, u1,
                       sb + OFF_VB(r) + ((ks * 16 + (lane & 15)) * QP + 64) * 2);
                mma_h(ssum[hf][0], ssum[hf][1], ssum[hf][2], ssum[hf][3],
                      pa0, pa1, pa2, pa3, u0, u1);

#pragma unroll
                for (int ntp = 0; ntp < 4; ntp++) {
                    uint32_t v0, v1, v2, v3;
                    ldsm4t(v0, v1, v2, v3,
                           sb + OFF_VB(r) +
                           ((ks * 16 + (lane & 15)) * QP + ntp * 16 +
                            ((lane >> 4) << 3)) * 2);
                    float* oa = o[hf][2 * ntp];
                    float* ob = o[hf][2 * ntp + 1];
                    mma_h(oa[0], oa[1], oa[2], oa[3], pa0, pa1, pa2, pa3, v0, v1);
                    mma_h(ob[0], ob[1], ob[2], ob[3], pa0, pa1, pa2, pa3, v2, v3);
                }
            }
        }
        r = (r == 2) ? 0 : r + 1;
    }
#undef STAGEKV

    // ---- finalize: ssum fragments hold exact row sums ----
#pragma unroll
    for (int hf = 0; hf < 2; hf++) {
        const float inv0 = 1.0f / ssum[hf][0], inv1 = 1.0f / ssum[hf][2];
        const int gr0 = q0 + hf * 128 + wid * 16 + (lane >> 2);
#pragma unroll
        for (int nt = 0; nt < 8; nt++) {
            const int col = h * Dd + nt * 8 + 2 * (lane & 3);
            const size_t i0 = ((size_t)b * Tq + gr0) * Cdim + col;
            const size_t i1 = ((size_t)b * Tq + gr0 + 8) * Cdim + col;
            *(uint32_t*)(g_Oh + i0) =
                pack2h(o[hf][nt][0] * inv0, o[hf][nt][1] * inv0);
            *(uint32_t*)(g_Oh + i1) =
                pack2h(o[hf][nt][2] * inv1, o[hf][nt][3] * inv1);
        }
    }
}

// ---------------------------------------------------------------------------
extern "C" void kernel_launch(void* const* d_in, const int* in_sizes, int n_in,
                              void* d_out, int out_size)
{
    (void)in_sizes; (void)n_in; (void)out_size;
    const float* x    = (const float*)d_in[0];
    const int*   mask = (const int*)d_in[1];
    const float* Wq = (const float*)d_in[2];
    const float* bq = (const float*)d_in[3];
    const float* Wk = (const float*)d_in[4];
    const float* bk = (const float*)d_in[5];
    const float* Wv = (const float*)d_in[6];
    const float* bv = (const float*)d_in[7];
    const float* Wp = (const float*)d_in[8];
    const float* bp = (const float*)d_in[9];
    float* out = (float*)d_out;

    static bool init = false;
    static __half *xh, *wh, *oh;
    if (!init) {
        cudaFuncSetAttribute(gemm_h,
            cudaFuncAttributeMaxDynamicSharedMemorySize, GEMM_SMEM2);
        cudaFuncSetAttribute(attn_h,
            cudaFuncAttributeMaxDynamicSharedMemorySize, ATT_SMEM_B);
        cudaGetSymbolAddress((void**)&xh, g_xh);
        cudaGetSymbolAddress((void**)&wh, g_Wh);
        cudaGetSymbolAddress((void**)&oh, g_Oh);
        init = true;
    }

    const int NX = Mrows * Cdim;   // 4194304
    const int NW = Cdim * Cdim;    // 1048576
    const size_t WN = (size_t)NW;

    cvt_kernel<<<NX / 2048, 256>>>(x, xh, NX);
    {
        dim3 g(NW / 2048, 4);
        cvt4_kernel<<<g, 256>>>(Wq, Wk, Wv, Wp, wh, NW);
    }

    // fused QKV projection: N = 3072 over packed Wq|Wk|Wv
    {
        dim3 g(3 * Cdim / 128, Mrows / 128);  // (24, 32)
        gemm_h<<<g, 256, GEMM_SMEM2>>>(xh, wh, bq, bk, bv, nullptr, 0);
    }

    {
        dim3 g(Tq / 256, Bsz * Hh);           // (8, 32)
        attn_h<<<g, 256, ATT_SMEM_B>>>(mask);
    }

    // output projection
    {
        dim3 g(Cdim / 128, Mrows / 128);      // (8, 32)
        gemm_h<<<g, 256, GEMM_SMEM2>>>(oh, wh + 3 * WN, bp, bp, bp, out, 1);
    }
}

// round 15
// speedup vs baseline: 1.2738x; 1.0650x over previous
#include <cuda_runtime.h>
#include <cuda_fp16.h>
#include <math.h>
#include <stdint.h>

// Problem constants
#define Bsz 2
#define Tq  2048
#define Cdim 1024
#define Hh  16
#define Dd  64
#define Mrows (Bsz*Tq)   // 4096

// ---------------------------------------------------------------------------
// Device-global scratch (sanctioned no-alloc path)
// ---------------------------------------------------------------------------
__device__ __align__(16) __half g_xh[Mrows*Cdim];
__device__ __align__(16) __half g_Wh[4*Cdim*Cdim];   // Wq,Wk,Wv,Wp packed
__device__ __align__(16) __half g_Qh[Mrows*Cdim];
__device__ __align__(16) __half g_Kh[Mrows*Cdim];
__device__ __align__(16) __half g_Vh[Mrows*Cdim];
__device__ __align__(16) __half g_Oh[Mrows*Cdim];

// ---------------------------------------------------------------------------
// Helpers (family-portable ISA)
// ---------------------------------------------------------------------------
__device__ __forceinline__ uint32_t smem_u32(const void* p) {
    uint32_t a;
    asm("{ .reg .u64 t; cvta.to.shared.u64 t, %1; cvt.u32.u64 %0, t; }"
        : "=r"(a) : "l"(p));
    return a;
}
__device__ __forceinline__ void cp16(uint32_t dst, const void* src) {
    asm volatile("cp.async.cg.shared.global [%0], [%1], 16;"
                 :: "r"(dst), "l"(src));
}
__device__ __forceinline__ void cp_commit() {
    asm volatile("cp.async.commit_group;");
}
template<int N> __device__ __forceinline__ void cp_wait() {
    asm volatile("cp.async.wait_group %0;" :: "n"(N));
}
__device__ __forceinline__ void mma_h(
    float& c0, float& c1, float& c2, float& c3,
    uint32_t a0, uint32_t a1, uint32_t a2, uint32_t a3,
    uint32_t b0, uint32_t b1)
{
    asm volatile(
        "mma.sync.aligned.m16n8k16.row.col.f32.f16.f16.f32 "
        "{%0,%1,%2,%3}, {%4,%5,%6,%7}, {%8,%9}, {%0,%1,%2,%3};"
        : "+f"(c0), "+f"(c1), "+f"(c2), "+f"(c3)
        : "r"(a0), "r"(a1), "r"(a2), "r"(a3), "r"(b0), "r"(b1));
}
__device__ __forceinline__ void ldsm4(
    uint32_t& r0, uint32_t& r1, uint32_t& r2, uint32_t& r3, uint32_t addr)
{
    asm volatile("ldmatrix.sync.aligned.m8n8.x4.shared.b16 {%0,%1,%2,%3}, [%4];"
        : "=r"(r0), "=r"(r1), "=r"(r2), "=r"(r3) : "r"(addr));
}
__device__ __forceinline__ void ldsm4t(
    uint32_t& r0, uint32_t& r1, uint32_t& r2, uint32_t& r3, uint32_t addr)
{
    asm volatile("ldmatrix.sync.aligned.m8n8.x4.trans.shared.b16 {%0,%1,%2,%3}, [%4];"
        : "=r"(r0), "=r"(r1), "=r"(r2), "=r"(r3) : "r"(addr));
}
__device__ __forceinline__ void ldsm2t(uint32_t& r0, uint32_t& r1, uint32_t addr)
{
    asm volatile("ldmatrix.sync.aligned.m8n8.x2.trans.shared.b16 {%0,%1}, [%2];"
        : "=r"(r0), "=r"(r1) : "r"(addr));
}
__device__ __forceinline__ uint32_t pack2h(float lo, float hi) {
    uint32_t r;
    asm("cvt.rn.f16x2.f32 %0, %1, %2;" : "=r"(r) : "f"(hi), "f"(lo));
    return r;
}
__device__ __forceinline__ float ex2f(float x) {
    float r;
    asm("ex2.approx.ftz.f32 %0, %1;" : "=f"(r) : "f"(x));
    return r;
}

// ---------------------------------------------------------------------------
// fp32 -> fp16 converts (round-10 versions)
// ---------------------------------------------------------------------------
__global__ void cvt_kernel(const float* __restrict__ src,
                           __half* __restrict__ dst, int n)
{
    int i = (blockIdx.x * blockDim.x + threadIdx.x) * 8;
    if (i >= n) return;
    float4 a = *(const float4*)(src + i);
    float4 b = *(const float4*)(src + i + 4);
    uint4 o;
    o.x = pack2h(a.x, a.y); o.y = pack2h(a.z, a.w);
    o.z = pack2h(b.x, b.y); o.w = pack2h(b.z, b.w);
    *(uint4*)(dst + i) = o;
}

__global__ void cvt4_kernel(const float* __restrict__ s0,
                            const float* __restrict__ s1,
                            const float* __restrict__ s2,
                            const float* __restrict__ s3,
                            __half* __restrict__ dst, int n)
{
    const float* s = (blockIdx.y == 0) ? s0 : (blockIdx.y == 1) ? s1
                   : (blockIdx.y == 2) ? s2 : s3;
    int i = (blockIdx.x * blockDim.x + threadIdx.x) * 8;
    if (i >= n) return;
    const size_t off = (size_t)blockIdx.y * n;
    float4 a = *(const float4*)(s + i);
    float4 b = *(const float4*)(s + i + 4);
    uint4 o;
    o.x = pack2h(a.x, a.y); o.y = pack2h(a.z, a.w);
    o.z = pack2h(b.x, b.y); o.w = pack2h(b.z, b.w);
    *(uint4*)(dst + off + i) = o;
}

// ---------------------------------------------------------------------------
// GEMM v4: CTA 256x128, 512 threads, 16 warps in 4(m)x4(n) — every warp runs
// the round-10-proven 64x32 microkernel. 25% fewer cp16 per MAC than the
// 128x128/256-thread version (staging (256+128) rows serves 256x128 outputs),
// same 16 warps/SM, same 3-stage cp.async ring, prefetch after compute.
// mode 0: fused QKV (W [3072,1024]); Q pre-scaled 0.125*log2e.
// mode 1: output projection, fp32 Cout, bias b0.
// ---------------------------------------------------------------------------
#define GP2 72
#define AARR2 (256*GP2*2)          // 36864 bytes (A: 256 rows)
#define WARR2 (128*GP2*2)          // 18432 bytes (W: 128 rows)
#define STG2B (AARR2 + WARR2)      // 55296 per stage
#define GEMM_SMEM2 (3*STG2B)       // 165888

__global__ __launch_bounds__(512, 1) void gemm_h(
    const __half* __restrict__ A, const __half* __restrict__ W,
    const float* __restrict__ b0, const float* __restrict__ b1,
    const float* __restrict__ b2, float* __restrict__ Cout, int mode)
{
    extern __shared__ char sm[];
    const uint32_t sb = smem_u32(sm);
    const int tid = threadIdx.x, lane = tid & 31, wid = tid >> 5;  // 16 warps
    const int wm = wid & 3, wn = wid >> 2;                         // 4x4
    const int m0 = blockIdx.y * 256, n0 = blockIdx.x * 128;

    // staging: A 256 rows (2 thr/row, 32 halfs = 4 cp16),
    //          W 128 rows (4 thr/row, 16 halfs = 2 cp16)
    const int arow = tid >> 1, acol = (tid & 1) * 32;
    const uint32_t aoff = (uint32_t)(arow * GP2 + acol) * 2;
    const int wrow = tid >> 2, wcol = (tid & 3) * 16;
    const uint32_t woff = (uint32_t)AARR2 + (uint32_t)(wrow * GP2 + wcol) * 2;
    const __half* Ar = A + (size_t)(m0 + arow) * Cdim + acol;
    const __half* Wr = W + (size_t)(n0 + wrow) * Cdim + wcol;

#define STG(kc, slot) do {                                        \
        uint32_t st_ = sb + (slot) * STG2B;                       \
        cp16(st_ + aoff,      Ar + (kc));                         \
        cp16(st_ + aoff + 16, Ar + (kc) + 8);                     \
        cp16(st_ + aoff + 32, Ar + (kc) + 16);                    \
        cp16(st_ + aoff + 48, Ar + (kc) + 24);                    \
        cp16(st_ + woff,      Wr + (kc));                         \
        cp16(st_ + woff + 16, Wr + (kc) + 8);                     \
        cp_commit();                                              \
    } while (0)

    float acc[4][4][4];
#pragma unroll
    for (int a = 0; a < 4; a++)
#pragma unroll
        for (int b = 0; b < 4; b++)
#pragma unroll
            for (int c = 0; c < 4; c++) acc[a][b][c] = 0.f;

    STG(0, 0); STG(64, 1);

    int slot_next = 2;
    for (int kt = 0; kt < 16; kt++) {
        if (kt < 14) cp_wait<1>(); else cp_wait<0>();
        __syncthreads();

        const int sl = kt - (kt / 3) * 3;   // kt mod 3
        const uint32_t stb = sb + sl * STG2B;

#pragma unroll
        for (int s = 0; s < 4; s++) {
            const uint32_t cg = s * 16 + ((lane >> 4) << 3);
            uint32_t bf[2][4], af[4][4];
#pragma unroll
            for (int ntp = 0; ntp < 2; ntp++)
                ldsm4(bf[ntp][0], bf[ntp][1], bf[ntp][2], bf[ntp][3],
                      stb + AARR2 +
                      ((wn * 32 + ntp * 16 + (lane & 15)) * GP2 + cg) * 2);
#pragma unroll
            for (int mt = 0; mt < 4; mt++)
                ldsm4(af[mt][0], af[mt][1], af[mt][2], af[mt][3],
                      stb + ((wm * 64 + mt * 16 + (lane & 15)) * GP2 + cg) * 2);
#pragma unroll
            for (int mt = 0; mt < 4; mt++)
#pragma unroll
                for (int nt = 0; nt < 4; nt++) {
                    float* c = acc[mt][nt];
                    mma_h(c[0], c[1], c[2], c[3],
                          af[mt][0], af[mt][1], af[mt][2], af[mt][3],
                          bf[nt >> 1][nt & 1], bf[nt >> 1][(nt & 1) + 2]);
                }
        }
        if (kt + 2 < 16) {
            STG((kt + 2) * 64, slot_next);
            slot_next = (slot_next == 2) ? 0 : slot_next + 1;
        }
    }
#undef STG

    // epilogue
    const int mat = n0 >> 10;  // constant per CTA (mode 0)
    const float* bb = (mat == 0) ? b0 : (mat == 1) ? b1 : b2;
    __half* dsth = (mat == 0) ? g_Qh : (mat == 1) ? g_Kh : g_Vh;
    // Q scale folds 1/sqrt(D) AND log2(e) so attention uses ex2 directly
    const float scale = (mat == 0) ? 0.125f * 1.4426950408889634f : 1.0f;

#pragma unroll
    for (int mt = 0; mt < 4; mt++) {
#pragma unroll
        for (int nt = 0; nt < 4; nt++) {
            float* c = acc[mt][nt];
            const int row = m0 + wm * 64 + mt * 16 + (lane >> 2);
            const int col = n0 + wn * 32 + nt * 8 + 2 * (lane & 3);
            if (mode == 1) {
                const float bv0 = b0[col], bv1 = b0[col + 1];
                *(float2*)(Cout + (size_t)row * Cdim + col) =
                    make_float2(c[0] + bv0, c[1] + bv1);
                *(float2*)(Cout + (size_t)(row + 8) * Cdim + col) =
                    make_float2(c[2] + bv0, c[3] + bv1);
            } else {
                const int mc = col & 1023;
                const float bv0 = bb[mc], bv1 = bb[mc + 1];
                const float v00 = (c[0] + bv0) * scale, v01 = (c[1] + bv1) * scale;
                const float v10 = (c[2] + bv0) * scale, v11 = (c[3] + bv1) * scale;
                const int hh = mc >> 6, d = mc & 63;
                const int bb0 = row >> 11, t0 = row & 2047;
                const int bb1 = (row + 8) >> 11, t1 = (row + 8) & 2047;
                const size_t i0 = (((size_t)(bb0 * Hh + hh)) * Tq + t0) * Dd + d;
                const size_t i1 = (((size_t)(bb1 * Hh + hh)) * Tq + t1) * Dd + d;
                *(uint32_t*)(dsth + i0) = pack2h(v00, v01);
                *(uint32_t*)(dsth + i1) = pack2h(v10, v11);
            }
        }
    }
}

// ---------------------------------------------------------------------------
// Flash attention, fp16 mma.sync, static softmax — EXACT round-10 version
// (118.2us, proven three times). Round-8 structure + bare ex2.
// ---------------------------------------------------------------------------
#define QP 72
#define QTILE (128*QP*2)           // 18432
#define KVARR (64*QP*2)            // 9216
#define OFF_Q 0
#define OFF_KB(s) (QTILE + (s)*2*KVARR)
#define OFF_VB(s) (QTILE + (s)*2*KVARR + KVARR)
#define OFF_MK (QTILE + 6*KVARR)
#define ATT_SMEM_B (OFF_MK + 3*64*4)   // 74496

__global__ __launch_bounds__(256, 2) void attn_h(const int* __restrict__ mask)
{
    extern __shared__ char sm[];
    const uint32_t sb = smem_u32(sm);
    const int tid = threadIdx.x, lane = tid & 31, wid = tid >> 5;
    const int bh = blockIdx.y;
    const int b  = bh >> 4, h = bh & 15;
    const int q0 = blockIdx.x * 128;
    int* Mk = (int*)(sm + OFF_MK);

    // ones columns (V cols 64..71, all 3 buffers) — written once.
    if (tid < 192) {
        const int s = tid >> 6, row = tid & 63;
        uint32_t* p = (uint32_t*)(sm + OFF_VB(s) + (row * QP + 64) * 2);
        p[0] = 0x3C003C00u; p[1] = 0x3C003C00u;
        p[2] = 0x3C003C00u; p[3] = 0x3C003C00u;
    }

    // Q staging: 128 rows, 2 threads/row, 4 cp16 each
    {
        const int qrow = tid >> 1, qcol = (tid & 1) * 32;
        const uint32_t qoff = (uint32_t)(qrow * QP + qcol) * 2;
        const __half* Qg = g_Qh + ((size_t)bh * Tq + q0 + qrow) * Dd + qcol;
#pragma unroll
        for (int j = 0; j < 4; j++)
            cp16(sb + OFF_Q + qoff + j * 16, Qg + j * 8);
        cp_commit();
    }

    // K/V staging coords: 64 rows, 4 threads/row, 2 cp16 per array
    const int krow = tid >> 2, kcol = (tid & 3) * 16;
    const uint32_t koff = (uint32_t)(krow * QP + kcol) * 2;

#define STAGEKV(kt, slot) do {                                                 \
        const __half* Kg_ = g_Kh + ((size_t)bh * Tq + (kt) * 64 + krow) * Dd + kcol; \
        const __half* Vg_ = g_Vh + ((size_t)bh * Tq + (kt) * 64 + krow) * Dd + kcol; \
        cp16(sb + OFF_KB(slot) + koff,      Kg_);                              \
        cp16(sb + OFF_KB(slot) + koff + 16, Kg_ + 8);                          \
        cp16(sb + OFF_VB(slot) + koff,      Vg_);                              \
        cp16(sb + OFF_VB(slot) + koff + 16, Vg_ + 8);                          \
        if (tid < 64) Mk[(slot) * 64 + tid] = mask[b * Tq + (kt) * 64 + tid];  \
        cp_commit();                                                           \
    } while (0)

    STAGEKV(0, 0);
    STAGEKV(1, 1);
    cp_wait<2>();       // Q landed (pending: s0, s1)
    __syncthreads();

    // hoist Q fragments (loop-invariant): warp covers rows wid*16..wid*16+15
    uint32_t qf[4][4];
#pragma unroll
    for (int ks = 0; ks < 4; ks++)
        ldsm4(qf[ks][0], qf[ks][1], qf[ks][2], qf[ks][3],
              sb + OFF_Q +
              ((wid * 16 + (lane & 15)) * QP + ks * 16 + ((lane >> 4) << 3)) * 2);

    float o[8][4];
#pragma unroll
    for (int nt = 0; nt < 8; nt++)
#pragma unroll
        for (int c = 0; c < 4; c++) o[nt][c] = 0.f;
    float ssum[4] = {0.f, 0.f, 0.f, 0.f};   // row-sum fragment (ones-col MMA)

    const int NT = Tq / 64;   // 32
    int r = 0, snext = 2;
    for (int kt = 0; kt < NT; kt++) {
        if (kt < NT - 1) cp_wait<1>(); else cp_wait<0>();
        __syncthreads();   // buffer r ready; also releases slot snext
        if (kt + 2 < NT) {
            STAGEKV(kt + 2, snext);
            snext = (snext == 2) ? 0 : snext + 1;
        }

        // ---- S = Q K^T ----
        float s[8][4];
#pragma unroll
        for (int nt = 0; nt < 8; nt++)
#pragma unroll
            for (int c = 0; c < 4; c++) s[nt][c] = 0.f;

#pragma unroll
        for (int ks = 0; ks < 4; ks++) {
#pragma unroll
            for (int ntp = 0; ntp < 4; ntp++) {
                uint32_t k0, k1, k2, k3;
                ldsm4(k0, k1, k2, k3,
                      sb + OFF_KB(r) +
                      ((ntp * 16 + (lane & 15)) * QP + ks * 16 + ((lane >> 4) << 3)) * 2);
                float* sa = s[2 * ntp];
                float* sc = s[2 * ntp + 1];
                mma_h(sa[0], sa[1], sa[2], sa[3],
                      qf[ks][0], qf[ks][1], qf[ks][2], qf[ks][3], k0, k2);
                mma_h(sc[0], sc[1], sc[2], sc[3],
                      qf[ks][0], qf[ks][1], qf[ks][2], qf[ks][3], k1, k3);
            }
        }

        // ---- mask (warp-uniform all-ones fast path) ----
        const int* mk = Mk + r * 64;
        const bool allone = __all_sync(0xffffffffu,
                (mk[lane] != 0) & (mk[lane + 32] != 0));
        if (!allone) {
            const int c0 = 2 * (lane & 3);
#pragma unroll
            for (int nt = 0; nt < 8; nt++) {
                if (!mk[nt * 8 + c0])     { s[nt][0] = -1e30f; s[nt][2] = -1e30f; }
                if (!mk[nt * 8 + c0 + 1]) { s[nt][1] = -1e30f; s[nt][3] = -1e30f; }
            }
        }

        // ---- static softmax: P = 2^S (Q carries log2e; bare MUFU) ----
#pragma unroll
        for (int nt = 0; nt < 8; nt++) {
            s[nt][0] = ex2f(s[nt][0]);
            s[nt][1] = ex2f(s[nt][1]);
            s[nt][2] = ex2f(s[nt][2]);
            s[nt][3] = ex2f(s[nt][3]);
        }

        // ---- O += P V ; ssum += P @ ones ----
#pragma unroll
        for (int ks = 0; ks < 4; ks++) {
            uint32_t pa0 = pack2h(s[2 * ks][0],     s[2 * ks][1]);
            uint32_t pa1 = pack2h(s[2 * ks][2],     s[2 * ks][3]);
            uint32_t pa2 = pack2h(s[2 * ks + 1][0], s[2 * ks + 1][1]);
            uint32_t pa3 = pack2h(s[2 * ks + 1][2], s[2 * ks + 1][3]);

            uint32_t u0, u1;   // ones-column B fragment (cols 64..71)
            ldsm2t(u0, u1,
                   sb + OFF_VB(r) + ((ks * 16 + (lane & 15)) * QP + 64) * 2);
            mma_h(ssum[0], ssum[1], ssum[2], ssum[3], pa0, pa1, pa2, pa3, u0, u1);

#pragma unroll
            for (int ntp = 0; ntp < 4; ntp++) {
                uint32_t v0, v1, v2, v3;
                ldsm4t(v0, v1, v2, v3,
                       sb + OFF_VB(r) +
                       ((ks * 16 + (lane & 15)) * QP + ntp * 16 + ((lane >> 4) << 3)) * 2);
                float* oa = o[2 * ntp];
                float* ob = o[2 * ntp + 1];
                mma_h(oa[0], oa[1], oa[2], oa[3], pa0, pa1, pa2, pa3, v0, v1);
                mma_h(ob[0], ob[1], ob[2], ob[3], pa0, pa1, pa2, pa3, v2, v3);
            }
        }
        r = (r == 2) ? 0 : r + 1;
    }
#undef STAGEKV

    // ---- finalize: ssum fragment already holds exact row sums ----
    const float inv0 = 1.0f / ssum[0], inv1 = 1.0f / ssum[2];
    const int gr0 = q0 + wid * 16 + (lane >> 2);
#pragma unroll
    for (int nt = 0; nt < 8; nt++) {
        const int col = h * Dd + nt * 8 + 2 * (lane & 3);
        const size_t i0 = ((size_t)b * Tq + gr0) * Cdim + col;
        const size_t i1 = ((size_t)b * Tq + gr0 + 8) * Cdim + col;
        *(uint32_t*)(g_Oh + i0) = pack2h(o[nt][0] * inv0, o[nt][1] * inv0);
        *(uint32_t*)(g_Oh + i1) = pack2h(o[nt][2] * inv1, o[nt][3] * inv1);
    }
}

// ---------------------------------------------------------------------------
extern "C" void kernel_launch(void* const* d_in, const int* in_sizes, int n_in,
                              void* d_out, int out_size)
{
    (void)in_sizes; (void)n_in; (void)out_size;
    const float* x    = (const float*)d_in[0];
    const int*   mask = (const int*)d_in[1];
    const float* Wq = (const float*)d_in[2];
    const float* bq = (const float*)d_in[3];
    const float* Wk = (const float*)d_in[4];
    const float* bk = (const float*)d_in[5];
    const float* Wv = (const float*)d_in[6];
    const float* bv = (const float*)d_in[7];
    const float* Wp = (const float*)d_in[8];
    const float* bp = (const float*)d_in[9];
    float* out = (float*)d_out;

    static bool init = false;
    static __half *xh, *wh, *oh;
    if (!init) {
        cudaFuncSetAttribute(gemm_h,
            cudaFuncAttributeMaxDynamicSharedMemorySize, GEMM_SMEM2);
        cudaFuncSetAttribute(attn_h,
            cudaFuncAttributeMaxDynamicSharedMemorySize, ATT_SMEM_B);
        cudaGetSymbolAddress((void**)&xh, g_xh);
        cudaGetSymbolAddress((void**)&wh, g_Wh);
        cudaGetSymbolAddress((void**)&oh, g_Oh);
        init = true;
    }

    const int NX = Mrows * Cdim;   // 4194304
    const int NW = Cdim * Cdim;    // 1048576
    const size_t WN = (size_t)NW;

    cvt_kernel<<<NX / 2048, 256>>>(x, xh, NX);
    {
        dim3 g(NW / 2048, 4);
        cvt4_kernel<<<g, 256>>>(Wq, Wk, Wv, Wp, wh, NW);
    }

    // fused QKV projection: N = 3072 over packed Wq|Wk|Wv, M-tile 256
    {
        dim3 g(3 * Cdim / 128, Mrows / 256);  // (24, 16)
        gemm_h<<<g, 512, GEMM_SMEM2>>>(xh, wh, bq, bk, bv, nullptr, 0);
    }

    {
        dim3 g(Tq / 128, Bsz * Hh);           // (16, 32)
        attn_h<<<g, 256, ATT_SMEM_B>>>(mask);
    }

    // output projection
    {
        dim3 g(Cdim / 128, Mrows / 256);      // (8, 16)
        gemm_h<<<g, 512, GEMM_SMEM2>>>(oh, wh + 3 * WN, bp, bp, bp, out, 1);
    }
}

// round 16
// speedup vs baseline: 1.2852x; 1.0089x over previous
#include <cuda_runtime.h>
#include <cuda_fp16.h>
#include <math.h>
#include <stdint.h>

// Problem constants
#define Bsz 2
#define Tq  2048
#define Cdim 1024
#define Hh  16
#define Dd  64
#define Mrows (Bsz*Tq)   // 4096

// ---------------------------------------------------------------------------
// Device-global scratch (sanctioned no-alloc path)
// ---------------------------------------------------------------------------
__device__ __align__(16) __half g_xh[Mrows*Cdim];
__device__ __align__(16) __half g_Wh[4*Cdim*Cdim];   // Wq,Wk,Wv,Wp packed
__device__ __align__(16) __half g_Qh[Mrows*Cdim];
__device__ __align__(16) __half g_Kh[Mrows*Cdim];
__device__ __align__(16) __half g_Vh[Mrows*Cdim];
__device__ __align__(16) __half g_Oh[Mrows*Cdim];

// ---------------------------------------------------------------------------
// Helpers (family-portable ISA)
// ---------------------------------------------------------------------------
__device__ __forceinline__ uint32_t smem_u32(const void* p) {
    uint32_t a;
    asm("{ .reg .u64 t; cvta.to.shared.u64 t, %1; cvt.u32.u64 %0, t; }"
        : "=r"(a) : "l"(p));
    return a;
}
__device__ __forceinline__ void cp16(uint32_t dst, const void* src) {
    asm volatile("cp.async.cg.shared.global [%0], [%1], 16;"
                 :: "r"(dst), "l"(src));
}
__device__ __forceinline__ void cp_commit() {
    asm volatile("cp.async.commit_group;");
}
template<int N> __device__ __forceinline__ void cp_wait() {
    asm volatile("cp.async.wait_group %0;" :: "n"(N));
}
__device__ __forceinline__ void mma_h(
    float& c0, float& c1, float& c2, float& c3,
    uint32_t a0, uint32_t a1, uint32_t a2, uint32_t a3,
    uint32_t b0, uint32_t b1)
{
    asm volatile(
        "mma.sync.aligned.m16n8k16.row.col.f32.f16.f16.f32 "
        "{%0,%1,%2,%3}, {%4,%5,%6,%7}, {%8,%9}, {%0,%1,%2,%3};"
        : "+f"(c0), "+f"(c1), "+f"(c2), "+f"(c3)
        : "r"(a0), "r"(a1), "r"(a2), "r"(a3), "r"(b0), "r"(b1));
}
__device__ __forceinline__ void ldsm4(
    uint32_t& r0, uint32_t& r1, uint32_t& r2, uint32_t& r3, uint32_t addr)
{
    asm volatile("ldmatrix.sync.aligned.m8n8.x4.shared.b16 {%0,%1,%2,%3}, [%4];"
        : "=r"(r0), "=r"(r1), "=r"(r2), "=r"(r3) : "r"(addr));
}
__device__ __forceinline__ void ldsm4t(
    uint32_t& r0, uint32_t& r1, uint32_t& r2, uint32_t& r3, uint32_t addr)
{
    asm volatile("ldmatrix.sync.aligned.m8n8.x4.trans.shared.b16 {%0,%1,%2,%3}, [%4];"
        : "=r"(r0), "=r"(r1), "=r"(r2), "=r"(r3) : "r"(addr));
}
__device__ __forceinline__ void ldsm2t(uint32_t& r0, uint32_t& r1, uint32_t addr)
{
    asm volatile("ldmatrix.sync.aligned.m8n8.x2.trans.shared.b16 {%0,%1}, [%2];"
        : "=r"(r0), "=r"(r1) : "r"(addr));
}
__device__ __forceinline__ uint32_t pack2h(float lo, float hi) {
    uint32_t r;
    asm("cvt.rn.f16x2.f32 %0, %1, %2;" : "=r"(r) : "f"(hi), "f"(lo));
    return r;
}
__device__ __forceinline__ float ex2f(float x) {
    float r;
    asm("ex2.approx.ftz.f32 %0, %1;" : "=f"(r) : "f"(x));
    return r;
}

// ---------------------------------------------------------------------------
// Fused fp32 -> fp16 convert: 8 uniform 1M-element segments, 16 elems/thread.
// y = 0..3 -> quarters of x into g_xh; y = 4..7 -> Wq/Wk/Wv/Wp into g_Wh.
// ---------------------------------------------------------------------------
#define SEG (Cdim*Cdim)   // 1048576

__global__ void cvt_all(const float* __restrict__ x,
                        const float* __restrict__ w0,
                        const float* __restrict__ w1,
                        const float* __restrict__ w2,
                        const float* __restrict__ w3,
                        __half* __restrict__ xh,
                        __half* __restrict__ wh)
{
    const int y = blockIdx.y;
    const float* src;
    __half* dst;
    if (y < 4) { src = x + (size_t)y * SEG;        dst = xh + (size_t)y * SEG; }
    else {
        src = (y == 4) ? w0 : (y == 5) ? w1 : (y == 6) ? w2 : w3;
        dst = wh + (size_t)(y - 4) * SEG;
    }
    const int i = (blockIdx.x * blockDim.x + threadIdx.x) * 16;
    float4 a = *(const float4*)(src + i);
    float4 b = *(const float4*)(src + i + 4);
    float4 c = *(const float4*)(src + i + 8);
    float4 d = *(const float4*)(src + i + 12);
    uint4 o0, o1;
    o0.x = pack2h(a.x, a.y); o0.y = pack2h(a.z, a.w);
    o0.z = pack2h(b.x, b.y); o0.w = pack2h(b.z, b.w);
    o1.x = pack2h(c.x, c.y); o1.y = pack2h(c.z, c.w);
    o1.z = pack2h(d.x, d.y); o1.w = pack2h(d.z, d.w);
    *(uint4*)(dst + i)     = o0;
    *(uint4*)(dst + i + 8) = o1;
}

// ---------------------------------------------------------------------------
// GEMM (round-15 winner + 4-stage ring): CTA 256x128, 512 threads, 16 warps
// 4(m)x4(n), each the proven 64x32 microkernel. BK=64, 4-stage cp.async ring
// (3 chunks in flight via cp_wait<2> — keeps LDGSTS issue saturated through
// barriers), prefetch after compute (slot (kt+3)&3 last read at kt-1, kt-top
// barrier intervenes). 1 CTA/SM = 16 warps, smem 221KB.
// mode 0: fused QKV (W [3072,1024]); Q pre-scaled 0.125*log2e.
// mode 1: output projection, fp32 Cout, bias b0.
// ---------------------------------------------------------------------------
#define GP2 72
#define AARR2 (256*GP2*2)          // 36864 bytes (A: 256 rows)
#define WARR2 (128*GP2*2)          // 18432 bytes (W: 128 rows)
#define STG2B (AARR2 + WARR2)      // 55296 per stage
#define GEMM_SMEM2 (4*STG2B)       // 221184

__global__ __launch_bounds__(512, 1) void gemm_h(
    const __half* __restrict__ A, const __half* __restrict__ W,
    const float* __restrict__ b0, const float* __restrict__ b1,
    const float* __restrict__ b2, float* __restrict__ Cout, int mode)
{
    extern __shared__ char sm[];
    const uint32_t sb = smem_u32(sm);
    const int tid = threadIdx.x, lane = tid & 31, wid = tid >> 5;  // 16 warps
    const int wm = wid & 3, wn = wid >> 2;                         // 4x4
    const int m0 = blockIdx.y * 256, n0 = blockIdx.x * 128;

    // staging: A 256 rows (2 thr/row, 32 halfs = 4 cp16),
    //          W 128 rows (4 thr/row, 16 halfs = 2 cp16)
    const int arow = tid >> 1, acol = (tid & 1) * 32;
    const uint32_t aoff = (uint32_t)(arow * GP2 + acol) * 2;
    const int wrow = tid >> 2, wcol = (tid & 3) * 16;
    const uint32_t woff = (uint32_t)AARR2 + (uint32_t)(wrow * GP2 + wcol) * 2;
    const __half* Ar = A + (size_t)(m0 + arow) * Cdim + acol;
    const __half* Wr = W + (size_t)(n0 + wrow) * Cdim + wcol;

#define STG(kc, slot) do {                                        \
        uint32_t st_ = sb + (slot) * STG2B;                       \
        cp16(st_ + aoff,      Ar + (kc));                         \
        cp16(st_ + aoff + 16, Ar + (kc) + 8);                     \
        cp16(st_ + aoff + 32, Ar + (kc) + 16);                    \
        cp16(st_ + aoff + 48, Ar + (kc) + 24);                    \
        cp16(st_ + woff,      Wr + (kc));                         \
        cp16(st_ + woff + 16, Wr + (kc) + 8);                     \
        cp_commit();                                              \
    } while (0)

    float acc[4][4][4];
#pragma unroll
    for (int a = 0; a < 4; a++)
#pragma unroll
        for (int b = 0; b < 4; b++)
#pragma unroll
            for (int c = 0; c < 4; c++) acc[a][b][c] = 0.f;

    STG(0, 0); STG(64, 1); STG(128, 2);

    for (int kt = 0; kt < 16; kt++) {
        if (kt < 14) cp_wait<2>();
        else if (kt == 14) cp_wait<1>();
        else cp_wait<0>();
        __syncthreads();               // chunk kt resident

        const uint32_t stb = sb + (kt & 3) * STG2B;

#pragma unroll
        for (int s = 0; s < 4; s++) {
            const uint32_t cg = s * 16 + ((lane >> 4) << 3);
            uint32_t bf[2][4], af[4][4];
#pragma unroll
            for (int ntp = 0; ntp < 2; ntp++)
                ldsm4(bf[ntp][0], bf[ntp][1], bf[ntp][2], bf[ntp][3],
                      stb + AARR2 +
                      ((wn * 32 + ntp * 16 + (lane & 15)) * GP2 + cg) * 2);
#pragma unroll
            for (int mt = 0; mt < 4; mt++)
                ldsm4(af[mt][0], af[mt][1], af[mt][2], af[mt][3],
                      stb + ((wm * 64 + mt * 16 + (lane & 15)) * GP2 + cg) * 2);
#pragma unroll
            for (int mt = 0; mt < 4; mt++)
#pragma unroll
                for (int nt = 0; nt < 4; nt++) {
                    float* c = acc[mt][nt];
                    mma_h(c[0], c[1], c[2], c[3],
                          af[mt][0], af[mt][1], af[mt][2], af[mt][3],
                          bf[nt >> 1][nt & 1], bf[nt >> 1][(nt & 1) + 2]);
                }
        }
        if (kt + 3 < 16)
            STG((kt + 3) * 64, (kt + 3) & 3);
    }
#undef STG

    // epilogue
    const int mat = n0 >> 10;  // constant per CTA (mode 0)
    const float* bb = (mat == 0) ? b0 : (mat == 1) ? b1 : b2;
    __half* dsth = (mat == 0) ? g_Qh : (mat == 1) ? g_Kh : g_Vh;
    // Q scale folds 1/sqrt(D) AND log2(e) so attention uses ex2 directly
    const float scale = (mat == 0) ? 0.125f * 1.4426950408889634f : 1.0f;

#pragma unroll
    for (int mt = 0; mt < 4; mt++) {
#pragma unroll
        for (int nt = 0; nt < 4; nt++) {
            float* c = acc[mt][nt];
            const int row = m0 + wm * 64 + mt * 16 + (lane >> 2);
            const int col = n0 + wn * 32 + nt * 8 + 2 * (lane & 3);
            if (mode == 1) {
                const float bv0 = b0[col], bv1 = b0[col + 1];
                *(float2*)(Cout + (size_t)row * Cdim + col) =
                    make_float2(c[0] + bv0, c[1] + bv1);
                *(float2*)(Cout + (size_t)(row + 8) * Cdim + col) =
                    make_float2(c[2] + bv0, c[3] + bv1);
            } else {
                const int mc = col & 1023;
                const float bv0 = bb[mc], bv1 = bb[mc + 1];
                const float v00 = (c[0] + bv0) * scale, v01 = (c[1] + bv1) * scale;
                const float v10 = (c[2] + bv0) * scale, v11 = (c[3] + bv1) * scale;
                const int hh = mc >> 6, d = mc & 63;
                const int bb0 = row >> 11, t0 = row & 2047;
                const int bb1 = (row + 8) >> 11, t1 = (row + 8) & 2047;
                const size_t i0 = (((size_t)(bb0 * Hh + hh)) * Tq + t0) * Dd + d;
                const size_t i1 = (((size_t)(bb1 * Hh + hh)) * Tq + t1) * Dd + d;
                *(uint32_t*)(dsth + i0) = pack2h(v00, v01);
                *(uint32_t*)(dsth + i1) = pack2h(v10, v11);
            }
        }
    }
}

// ---------------------------------------------------------------------------
// Flash attention, fp16 mma.sync, static softmax — EXACT round-10 version
// (119us, proven four times). Round-8 structure + bare ex2.
// ---------------------------------------------------------------------------
#define QP 72
#define QTILE (128*QP*2)           // 18432
#define KVARR (64*QP*2)            // 9216
#define OFF_Q 0
#define OFF_KB(s) (QTILE + (s)*2*KVARR)
#define OFF_VB(s) (QTILE + (s)*2*KVARR + KVARR)
#define OFF_MK (QTILE + 6*KVARR)
#define ATT_SMEM_B (OFF_MK + 3*64*4)   // 74496

__global__ __launch_bounds__(256, 2) void attn_h(const int* __restrict__ mask)
{
    extern __shared__ char sm[];
    const uint32_t sb = smem_u32(sm);
    const int tid = threadIdx.x, lane = tid & 31, wid = tid >> 5;
    const int bh = blockIdx.y;
    const int b  = bh >> 4, h = bh & 15;
    const int q0 = blockIdx.x * 128;
    int* Mk = (int*)(sm + OFF_MK);

    // ones columns (V cols 64..71, all 3 buffers) — written once.
    if (tid < 192) {
        const int s = tid >> 6, row = tid & 63;
        uint32_t* p = (uint32_t*)(sm + OFF_VB(s) + (row * QP + 64) * 2);
        p[0] = 0x3C003C00u; p[1] = 0x3C003C00u;
        p[2] = 0x3C003C00u; p[3] = 0x3C003C00u;
    }

    // Q staging: 128 rows, 2 threads/row, 4 cp16 each
    {
        const int qrow = tid >> 1, qcol = (tid & 1) * 32;
        const uint32_t qoff = (uint32_t)(qrow * QP + qcol) * 2;
        const __half* Qg = g_Qh + ((size_t)bh * Tq + q0 + qrow) * Dd + qcol;
#pragma unroll
        for (int j = 0; j < 4; j++)
            cp16(sb + OFF_Q + qoff + j * 16, Qg + j * 8);
        cp_commit();
    }

    // K/V staging coords: 64 rows, 4 threads/row, 2 cp16 per array
    const int krow = tid >> 2, kcol = (tid & 3) * 16;
    const uint32_t koff = (uint32_t)(krow * QP + kcol) * 2;

#define STAGEKV(kt, slot) do {                                                 \
        const __half* Kg_ = g_Kh + ((size_t)bh * Tq + (kt) * 64 + krow) * Dd + kcol; \
        const __half* Vg_ = g_Vh + ((size_t)bh * Tq + (kt) * 64 + krow) * Dd + kcol; \
        cp16(sb + OFF_KB(slot) + koff,      Kg_);                              \
        cp16(sb + OFF_KB(slot) + koff + 16, Kg_ + 8);                          \
        cp16(sb + OFF_VB(slot) + koff,      Vg_);                              \
        cp16(sb + OFF_VB(slot) + koff + 16, Vg_ + 8);                          \
        if (tid < 64) Mk[(slot) * 64 + tid] = mask[b * Tq + (kt) * 64 + tid];  \
        cp_commit();                                                           \
    } while (0)

    STAGEKV(0, 0);
    STAGEKV(1, 1);
    cp_wait<2>();       // Q landed (pending: s0, s1)
    __syncthreads();

    // hoist Q fragments (loop-invariant): warp covers rows wid*16..wid*16+15
    uint32_t qf[4][4];
#pragma unroll
    for (int ks = 0; ks < 4; ks++)
        ldsm4(qf[ks][0], qf[ks][1], qf[ks][2], qf[ks][3],
              sb + OFF_Q +
              ((wid * 16 + (lane & 15)) * QP + ks * 16 + ((lane >> 4) << 3)) * 2);

    float o[8][4];
#pragma unroll
    for (int nt = 0; nt < 8; nt++)
#pragma unroll
        for (int c = 0; c < 4; c++) o[nt][c] = 0.f;
    float ssum[4] = {0.f, 0.f, 0.f, 0.f};   // row-sum fragment (ones-col MMA)

    const int NT = Tq / 64;   // 32
    int r = 0, snext = 2;
    for (int kt = 0; kt < NT; kt++) {
        if (kt < NT - 1) cp_wait<1>(); else cp_wait<0>();
        __syncthreads();   // buffer r ready; also releases slot snext
        if (kt + 2 < NT) {
            STAGEKV(kt + 2, snext);
            snext = (snext == 2) ? 0 : snext + 1;
        }

        // ---- S = Q K^T ----
        float s[8][4];
#pragma unroll
        for (int nt = 0; nt < 8; nt++)
#pragma unroll
            for (int c = 0; c < 4; c++) s[nt][c] = 0.f;

#pragma unroll
        for (int ks = 0; ks < 4; ks++) {
#pragma unroll
            for (int ntp = 0; ntp < 4; ntp++) {
                uint32_t k0, k1, k2, k3;
                ldsm4(k0, k1, k2, k3,
                      sb + OFF_KB(r) +
                      ((ntp * 16 + (lane & 15)) * QP + ks * 16 + ((lane >> 4) << 3)) * 2);
                float* sa = s[2 * ntp];
                float* sc = s[2 * ntp + 1];
                mma_h(sa[0], sa[1], sa[2], sa[3],
                      qf[ks][0], qf[ks][1], qf[ks][2], qf[ks][3], k0, k2);
                mma_h(sc[0], sc[1], sc[2], sc[3],
                      qf[ks][0], qf[ks][1], qf[ks][2], qf[ks][3], k1, k3);
            }
        }

        // ---- mask (warp-uniform all-ones fast path) ----
        const int* mk = Mk + r * 64;
        const bool allone = __all_sync(0xffffffffu,
                (mk[lane] != 0) & (mk[lane + 32] != 0));
        if (!allone) {
            const int c0 = 2 * (lane & 3);
#pragma unroll
            for (int nt = 0; nt < 8; nt++) {
                if (!mk[nt * 8 + c0])     { s[nt][0] = -1e30f; s[nt][2] = -1e30f; }
                if (!mk[nt * 8 + c0 + 1]) { s[nt][1] = -1e30f; s[nt][3] = -1e30f; }
            }
        }

        // ---- static softmax: P = 2^S (Q carries log2e; bare MUFU) ----
#pragma unroll
        for (int nt = 0; nt < 8; nt++) {
            s[nt][0] = ex2f(s[nt][0]);
            s[nt][1] = ex2f(s[nt][1]);
            s[nt][2] = ex2f(s[nt][2]);
            s[nt][3] = ex2f(s[nt][3]);
        }

        // ---- O += P V ; ssum += P @ ones ----
#pragma unroll
        for (int ks = 0; ks < 4; ks++) {
            uint32_t pa0 = pack2h(s[2 * ks][0],     s[2 * ks][1]);
            uint32_t pa1 = pack2h(s[2 * ks][2],     s[2 * ks][3]);
            uint32_t pa2 = pack2h(s[2 * ks + 1][0], s[2 * ks + 1][1]);
            uint32_t pa3 = pack2h(s[2 * ks + 1][2], s[2 * ks + 1][3]);

            uint32_t u0, u1;   // ones-column B fragment (cols 64..71)
            ldsm2t(u0, u1,
                   sb + OFF_VB(r) + ((ks * 16 + (lane & 15)) * QP + 64) * 2);
            mma_h(ssum[0], ssum[1], ssum[2], ssum[3], pa0, pa1, pa2, pa3, u0, u1);

#pragma unroll
            for (int ntp = 0; ntp < 4; ntp++) {
                uint32_t v0, v1, v2, v3;
                ldsm4t(v0, v1, v2, v3,
                       sb + OFF_VB(r) +
                       ((ks * 16 + (lane & 15)) * QP + ntp * 16 + ((lane >> 4) << 3)) * 2);
                float* oa = o[2 * ntp];
                float* ob = o[2 * ntp + 1];
                mma_h(oa[0], oa[1], oa[2], oa[3], pa0, pa1, pa2, pa3, v0, v1);
                mma_h(ob[0], ob[1], ob[2], ob[3], pa0, pa1, pa2, pa3, v2, v3);
            }
        }
        r = (r == 2) ? 0 : r + 1;
    }
#undef STAGEKV

    // ---- finalize: ssum fragment already holds exact row sums ----
    const float inv0 = 1.0f / ssum[0], inv1 = 1.0f / ssum[2];
    const int gr0 = q0 + wid * 16 + (lane >> 2);
#pragma unroll
    for (int nt = 0; nt < 8; nt++) {
        const int col = h * Dd + nt * 8 + 2 * (lane & 3);
        const size_t i0 = ((size_t)b * Tq + gr0) * Cdim + col;
        const size_t i1 = ((size_t)b * Tq + gr0 + 8) * Cdim + col;
        *(uint32_t*)(g_Oh + i0) = pack2h(o[nt][0] * inv0, o[nt][1] * inv0);
        *(uint32_t*)(g_Oh + i1) = pack2h(o[nt][2] * inv1, o[nt][3] * inv1);
    }
}

// ---------------------------------------------------------------------------
extern "C" void kernel_launch(void* const* d_in, const int* in_sizes, int n_in,
                              void* d_out, int out_size)
{
    (void)in_sizes; (void)n_in; (void)out_size;
    const float* x    = (const float*)d_in[0];
    const int*   mask = (const int*)d_in[1];
    const float* Wq = (const float*)d_in[2];
    const float* bq = (const float*)d_in[3];
    const float* Wk = (const float*)d_in[4];
    const float* bk = (const float*)d_in[5];
    const float* Wv = (const float*)d_in[6];
    const float* bv = (const float*)d_in[7];
    const float* Wp = (const float*)d_in[8];
    const float* bp = (const float*)d_in[9];
    float* out = (float*)d_out;

    static bool init = false;
    static __half *xh, *wh, *oh;
    if (!init) {
        cudaFuncSetAttribute(gemm_h,
            cudaFuncAttributeMaxDynamicSharedMemorySize, GEMM_SMEM2);
        cudaFuncSetAttribute(attn_h,
            cudaFuncAttributeMaxDynamicSharedMemorySize, ATT_SMEM_B);
        cudaGetSymbolAddress((void**)&xh, g_xh);
        cudaGetSymbolAddress((void**)&wh, g_Wh);
        cudaGetSymbolAddress((void**)&oh, g_Oh);
        init = true;
    }

    const size_t WN = (size_t)SEG;   // 1048576

    // single fused convert launch: 8 segments x 1M elements, 16 elems/thread
    {
        dim3 g(SEG / 4096, 8);
        cvt_all<<<g, 256>>>(x, Wq, Wk, Wv, Wp, xh, wh);
    }

    // fused QKV projection: N = 3072 over packed Wq|Wk|Wv, M-tile 256
    {
        dim3 g(3 * Cdim / 128, Mrows / 256);  // (24, 16)
        gemm_h<<<g, 512, GEMM_SMEM2>>>(xh, wh, bq, bk, bv, nullptr, 0);
    }

    {
        dim3 g(Tq / 128, Bsz * Hh);           // (16, 32)
        attn_h<<<g, 256, ATT_SMEM_B>>>(mask);
    }

    // output projection
    {
        dim3 g(Cdim / 128, Mrows / 256);      // (8, 16)
        gemm_h<<<g, 512, GEMM_SMEM2>>>(oh, wh + 3 * WN, bp, bp, bp, out, 1);
    }
}